// round 1
// baseline (speedup 1.0000x reference)
#include <cuda_runtime.h>

#define HW    60
#define NPIX  3600
#define HIDC  64
#define FEATC 128
#define MSIZE (3600LL*3600LL)
#define SEG   8
#define SEGN  450   /* 3600/8 */

// ---------------- static device scratch (no allocations allowed) ----------------
__device__ float g_thetaA[16*6];
__device__ float g_thetaB[16*6];
__device__ float g_xw[16*3*NPIX];            // forward-warped inputs
__device__ float g_h1[16*HIDC*NPIX];         // conv3x3+relu
__device__ float g_y [16L*NPIX*FEATC];       // conv1x1, pixel-major [ib][p][d]
__device__ float g_F [16L*NPIX*FEATC];       // final features [inst*4+b][n][d]
__device__ float g_M [8L*3600*3600];         // [mat*4+b][n][m]; mat0=Mh, mat1=Mv  (~415MB)
__device__ float g_hmax[4*NPIX], g_hs[4*NPIX];
__device__ float g_vmax[4*NPIX], g_vs[4*NPIX];
__device__ float g_vmax_part[SEG*4*NPIX], g_vsum_part[SEG*4*NPIX];
__device__ float g_Spart[SEG*4*NPIX];

// Fast exp on the FMA pipe (no MUFU). Valid for x <= ~0 (all call sites), rel err ~2e-5.
__device__ __forceinline__ float fexp(float x) {
    float t = x * 1.4426950408889634f;        // log2(e)
    t = fmaxf(t, -125.0f);                    // underflow clamp (exp -> ~0)
    float r = floorf(t);
    float f = t - r;                          // [0,1)
    // 2^f : Taylor of e^{f ln2}, degree 6
    float p = 1.5403530e-4f;
    p = fmaf(p, f, 1.3333558e-3f);
    p = fmaf(p, f, 9.6181291e-3f);
    p = fmaf(p, f, 5.5504109e-2f);
    p = fmaf(p, f, 2.4022651e-1f);
    p = fmaf(p, f, 6.9314718e-1f);
    p = fmaf(p, f, 1.0f);
    int ei = (int)r;
    return __int_as_float((ei + 127) << 23) * p;
}

// ---------------- K0: per (inst,b) affine matrices ----------------
__global__ void theta_kernel(const float* __restrict__ noise, const int* __restrict__ swap) {
    int t = threadIdx.x;
    if (t >= 16) return;
    int i = t >> 2;
    const float* nz = noise + t * 9;          // noise[i][b][3][3], rows 0,1 used
    float a  = 1.f + 0.05f * nz[0], b = 0.05f * nz[1], c = 0.05f * nz[2];
    float d  = 0.05f * nz[3], e = 1.f + 0.05f * nz[4], f = 0.05f * nz[5];
    float id = 1.f / (a * e - b * d);
    float fwd[6] = {a, b, c, d, e, f};
    float bwd[6] = { e * id, -b * id, (b * f - c * e) * id,
                    -d * id,  a * id, (c * d - a * f) * id};
    bool s = (swap[i] == 1);
#pragma unroll
    for (int k = 0; k < 6; k++) {
        g_thetaA[t * 6 + k] = s ? bwd[k] : fwd[k];
        g_thetaB[t * 6 + k] = s ? fwd[k] : bwd[k];
    }
}

// ---------------- K1: forward grid_sample with fused roll ----------------
__global__ void fwd_sample_kernel(const float* __restrict__ inA, const float* __restrict__ inB,
                                  const int* __restrict__ u_roll, const int* __restrict__ v_roll) {
    int idx = blockIdx.x * blockDim.x + threadIdx.x;
    if (idx >= 16 * 3 * NPIX) return;
    int p  = idx % NPIX;
    int c  = (idx / NPIX) % 3;
    int ib = idx / (3 * NPIX);                // inst*4 + b
    int i  = ib >> 2, b = ib & 3;
    const float* T = g_thetaA + ib * 6;
    int r = p / HW, cc = p % HW;
    float xn = (2 * cc + 1) * (1.f / HW) - 1.f;
    float yn = (2 * r  + 1) * (1.f / HW) - 1.f;
    float gx = T[0] * xn + T[1] * yn + T[2];
    float gy = T[3] * xn + T[4] * yn + T[5];
    float x = (gx + 1.f) * (HW * 0.5f) - 0.5f;
    float y = (gy + 1.f) * (HW * 0.5f) - 0.5f;
    float x0f = floorf(x), y0f = floorf(y);
    int x0 = (int)x0f, y0 = (int)y0f;
    float wx1 = x - x0f, wx0 = 1.f - wx1;
    float wy1 = y - y0f, wy0 = 1.f - wy1;
    const float* src = ((i & 1) == 0) ? inA : inB;   // inst 0,2 -> a; 1,3 -> b
    src += (b * 3 + c) * NPIX;
    int u = u_roll[ib], v = v_roll[ib];
    float acc = 0.f;
#pragma unroll
    for (int ky = 0; ky < 2; ky++) {
        int iy = y0 + ky;
        if (iy < 0 || iy >= HW) continue;
        int ry = iy + u; if (ry >= HW) ry -= HW;
        float wy = ky ? wy1 : wy0;
#pragma unroll
        for (int kx = 0; kx < 2; kx++) {
            int ix = x0 + kx;
            if (ix < 0 || ix >= HW) continue;
            int rx = ix + v; if (rx >= HW) rx -= HW;
            acc += wy * (kx ? wx1 : wx0) * src[ry * HW + rx];
        }
    }
    g_xw[ib * 3 * NPIX + c * NPIX + p] = acc;
}

// ---------------- K2: conv3x3 (3->64) + relu, SAME/zero-pad ----------------
__global__ void conv3_kernel(const float* __restrict__ w1, const float* __restrict__ b1) {
    int idx = blockIdx.x * blockDim.x + threadIdx.x;
    if (idx >= 16 * HIDC * NPIX) return;
    int p  = idx % NPIX;
    int oc = (idx / NPIX) % HIDC;
    int ib = idx / (NPIX * HIDC);
    int r = p / HW, c = p % HW;
    const float* xin = g_xw + ib * 3 * NPIX;
    const float* wk  = w1 + oc * 27;
    float acc = b1[oc];
#pragma unroll
    for (int ci = 0; ci < 3; ci++)
#pragma unroll
        for (int dy = -1; dy <= 1; dy++) {
            int rr = r + dy;
            if (rr < 0 || rr >= HW) continue;
#pragma unroll
            for (int dx = -1; dx <= 1; dx++) {
                int c2 = c + dx;
                if (c2 < 0 || c2 >= HW) continue;
                acc += wk[ci * 9 + (dy + 1) * 3 + (dx + 1)] * xin[ci * NPIX + rr * HW + c2];
            }
        }
    g_h1[(ib * HIDC + oc) * NPIX + p] = fmaxf(acc, 0.f);
}

// ---------------- K3: conv1x1 (64->128) + bias, output pixel-major ----------------
__global__ void conv1_kernel(const float* __restrict__ w2, const float* __restrict__ b2) {
    int blk = blockIdx.x;                     // ib*3600 + p
    int ib = blk / NPIX, p = blk % NPIX;
    int d  = threadIdx.x;
    __shared__ float sh[HIDC];
    if (d < HIDC) sh[d] = g_h1[(ib * HIDC + d) * NPIX + p];
    __syncthreads();
    const float* wr = w2 + d * HIDC;
    float acc = b2[d];
#pragma unroll
    for (int h = 0; h < HIDC; h++) acc = fmaf(wr[h], sh[h], acc);
    g_y[((size_t)ib * NPIX + p) * FEATC + d] = acc;
}

// ---------------- K4: backward grid_sample (128ch) with fused inverse roll ----------------
__global__ void bwd_sample_kernel(const int* __restrict__ u_roll, const int* __restrict__ v_roll) {
    int blk = blockIdx.x;                     // ib*3600 + n
    int ib = blk / NPIX, n = blk % NPIX;
    int d  = threadIdx.x;
    __shared__ float wt[4];
    __shared__ int   pp[4];
    if (d == 0) {
        int u = u_roll[ib], v = v_roll[ib];
        int r = n / HW, c = n % HW;
        int rr = r - u; if (rr < 0) rr += HW;
        int cc = c - v; if (cc < 0) cc += HW;
        const float* T = g_thetaB + ib * 6;
        float xn = (2 * cc + 1) * (1.f / HW) - 1.f;
        float yn = (2 * rr + 1) * (1.f / HW) - 1.f;
        float gx = T[0] * xn + T[1] * yn + T[2];
        float gy = T[3] * xn + T[4] * yn + T[5];
        float x = (gx + 1.f) * (HW * 0.5f) - 0.5f;
        float y = (gy + 1.f) * (HW * 0.5f) - 0.5f;
        float x0f = floorf(x), y0f = floorf(y);
        int x0 = (int)x0f, y0 = (int)y0f;
        float wx1 = x - x0f, wx0 = 1.f - wx1;
        float wy1 = y - y0f, wy0 = 1.f - wy1;
#pragma unroll
        for (int k = 0; k < 4; k++) {
            int iy = y0 + (k >> 1), ix = x0 + (k & 1);
            bool ok = (iy >= 0 && iy < HW && ix >= 0 && ix < HW);
            pp[k] = ok ? (iy * HW + ix) : -1;
            wt[k] = ((k >> 1) ? wy1 : wy0) * ((k & 1) ? wx1 : wx0);
        }
    }
    __syncthreads();
    const float* yb = g_y + (size_t)ib * NPIX * FEATC;
    float acc = 0.f;
#pragma unroll
    for (int k = 0; k < 4; k++) {
        int q = pp[k];
        if (q >= 0) acc += wt[k] * yb[(size_t)q * FEATC + d];
    }
    g_F[((size_t)ib * NPIX + n) * FEATC + d] = acc;
}

// ---------------- K5: fp32 NT GEMM  M[z][n][m] = F_a[n]·F_b[m], 64x64 tiles ----------------
__global__ void gemm_kernel() {
    int z = blockIdx.z;                       // mat*4 + b
    int mat = z >> 2, b = z & 3;
    const float* A  = g_F + (size_t)((mat * 2)     * 4 + b) * NPIX * FEATC;
    const float* Bm = g_F + (size_t)((mat * 2 + 1) * 4 + b) * NPIX * FEATC;
    float* C = g_M + (size_t)z * MSIZE;
    int n0 = blockIdx.y * 64, m0 = blockIdx.x * 64;
    __shared__ float As[32][65];
    __shared__ float Bs[32][65];
    int t = threadIdx.x;
    int tx = t & 15, ty = t >> 4;
    int lk4 = t & 7, lrow = t >> 3;           // conflict-free transposed store (ld=65)
    float acc[4][4];
#pragma unroll
    for (int u = 0; u < 4; u++)
#pragma unroll
        for (int v = 0; v < 4; v++) acc[u][v] = 0.f;

    for (int kc = 0; kc < FEATC; kc += 32) {
#pragma unroll
        for (int it = 0; it < 2; ++it) {
            int row = lrow + it * 32;
            int gn = n0 + row;
            float4 va = (gn < NPIX) ? *(const float4*)(A + (size_t)gn * FEATC + kc + lk4 * 4)
                                    : make_float4(0, 0, 0, 0);
            As[lk4 * 4 + 0][row] = va.x; As[lk4 * 4 + 1][row] = va.y;
            As[lk4 * 4 + 2][row] = va.z; As[lk4 * 4 + 3][row] = va.w;
            int gm = m0 + row;
            float4 vb = (gm < NPIX) ? *(const float4*)(Bm + (size_t)gm * FEATC + kc + lk4 * 4)
                                    : make_float4(0, 0, 0, 0);
            Bs[lk4 * 4 + 0][row] = vb.x; Bs[lk4 * 4 + 1][row] = vb.y;
            Bs[lk4 * 4 + 2][row] = vb.z; Bs[lk4 * 4 + 3][row] = vb.w;
        }
        __syncthreads();
#pragma unroll
        for (int k = 0; k < 32; ++k) {
            float af[4], bf[4];
#pragma unroll
            for (int u = 0; u < 4; u++) af[u] = As[k][ty * 4 + u];
#pragma unroll
            for (int v = 0; v < 4; v++) bf[v] = Bs[k][tx * 4 + v];
#pragma unroll
            for (int u = 0; u < 4; u++)
#pragma unroll
                for (int v = 0; v < 4; v++) acc[u][v] = fmaf(af[u], bf[v], acc[u][v]);
        }
        __syncthreads();
    }
#pragma unroll
    for (int u = 0; u < 4; u++) {
        int gn = n0 + ty * 4 + u;
        if (gn >= NPIX) continue;
#pragma unroll
        for (int v = 0; v < 4; v++) {
            int gm = m0 + tx * 4 + v;
            if (gm < NPIX) C[(size_t)gn * NPIX + gm] = acc[u][v];
        }
    }
}

// ---------------- K6: Mh row stats (hmax, hs) ----------------
__global__ void rowstats_kernel() {
    int blk = blockIdx.x;                     // b*3600 + n
    int b = blk / NPIX, n = blk % NPIX;
    const float* row = g_M + (size_t)b * MSIZE + (size_t)n * NPIX;
    __shared__ float red[256];
    int t = threadIdx.x;
    float mx = -1e30f;
    for (int m = t; m < NPIX; m += 256) mx = fmaxf(mx, row[m]);
    red[t] = mx; __syncthreads();
    for (int s = 128; s > 0; s >>= 1) { if (t < s) red[t] = fmaxf(red[t], red[t + s]); __syncthreads(); }
    mx = red[0]; __syncthreads();
    float sum = 0.f;
    for (int m = t; m < NPIX; m += 256) sum += fexp(row[m] - mx);
    red[t] = sum; __syncthreads();
    for (int s = 128; s > 0; s >>= 1) { if (t < s) red[t] += red[t + s]; __syncthreads(); }
    if (t == 0) { g_hmax[blk] = mx; g_hs[blk] = 1.f / (red[0] + 1e-4f); }
}

// ---------------- K7a: Mv column stats, per-segment online logsumexp ----------------
__global__ void colstats_kernel() {
    int m = blockIdx.x * 256 + threadIdx.x;
    int b = blockIdx.y, seg = blockIdx.z;
    if (m >= NPIX) return;
    const float* Mv = g_M + (size_t)(4 + b) * MSIZE;
    float mx = -1e30f, s = 0.f;
    int n0 = seg * SEGN, n1 = n0 + SEGN;
    for (int n = n0; n < n1; n++) {
        float x = Mv[(size_t)n * NPIX + m];
        if (x > mx) { s = s * fexp(mx - x) + 1.f; mx = x; }
        else         s += fexp(x - mx);
    }
    g_vmax_part[(seg * 4 + b) * NPIX + m] = mx;
    g_vsum_part[(seg * 4 + b) * NPIX + m] = s;
}

// ---------------- K7b: merge column-stat segments ----------------
__global__ void colmerge_kernel() {
    int idx = blockIdx.x * blockDim.x + threadIdx.x;
    if (idx >= 4 * NPIX) return;
    int b = idx / NPIX, m = idx % NPIX;
    float mx = -1e30f, s = 0.f;
#pragma unroll
    for (int seg = 0; seg < SEG; seg++) {
        float pm = g_vmax_part[(seg * 4 + b) * NPIX + m];
        float ps = g_vsum_part[(seg * 4 + b) * NPIX + m];
        if (pm > mx) { s = s * fexp(mx - pm) + ps; mx = pm; }
        else           s += ps * fexp(pm - mx);
    }
    g_vmax[idx] = mx;
    g_vs[idx]   = 1.f / (s + 1e-4f);
}

// ---------------- K8: S[b,m] partial sums over n segments ----------------
__global__ void spart_kernel() {
    int m = blockIdx.x * 256 + threadIdx.x;
    int b = blockIdx.y, seg = blockIdx.z;
    if (m >= NPIX) return;
    const float* Mh = g_M + (size_t)b * MSIZE;
    const float* Mv = g_M + (size_t)(4 + b) * MSIZE;
    float vmaxm = g_vmax[b * NPIX + m];
    float s = 0.f;
    int n0 = seg * SEGN, n1 = n0 + SEGN;
    for (int n = n0; n < n1; n++) {
        float e = fexp(Mv[(size_t)n * NPIX + m] - vmaxm + Mh[(size_t)n * NPIX + m] - g_hmax[b * NPIX + n]);
        s = fmaf(e, g_hs[b * NPIX + n], s);
    }
    g_Spart[(seg * 4 + b) * NPIX + m] = s;
}

// ---------------- K9: deterministic final reduction -> scalar mean ----------------
__global__ void final_kernel(float* __restrict__ out) {
    __shared__ float red[256];
    int t = threadIdx.x;
    float acc = 0.f;
    for (int idx = t; idx < 4 * NPIX; idx += 256) {
        int b = idx / NPIX, m = idx % NPIX;
        float S = 0.f;
#pragma unroll
        for (int seg = 0; seg < SEG; seg++) S += g_Spart[(seg * 4 + b) * NPIX + m];
        acc += logf(S * g_vs[idx] + 1e-4f);
    }
    red[t] = acc; __syncthreads();
    for (int s = 128; s > 0; s >>= 1) { if (t < s) red[t] += red[t + s]; __syncthreads(); }
    if (t == 0) out[0] = red[0] * (1.f / (4.f * NPIX));
}

// ---------------- launch ----------------
extern "C" void kernel_launch(void* const* d_in, const int* in_sizes, int n_in,
                              void* d_out, int out_size) {
    const float* input_a = (const float*)d_in[0];
    const float* input_b = (const float*)d_in[1];
    const float* w1      = (const float*)d_in[2];
    const float* b1      = (const float*)d_in[3];
    const float* w2      = (const float*)d_in[4];
    const float* b2      = (const float*)d_in[5];
    const float* noise   = (const float*)d_in[6];
    const int*   u_roll  = (const int*)d_in[7];
    const int*   v_roll  = (const int*)d_in[8];
    const int*   swap    = (const int*)d_in[9];
    float* out = (float*)d_out;

    theta_kernel<<<1, 32>>>(noise, swap);
    fwd_sample_kernel<<<(16 * 3 * NPIX + 255) / 256, 256>>>(input_a, input_b, u_roll, v_roll);
    conv3_kernel<<<(16 * HIDC * NPIX + 255) / 256, 256>>>(w1, b1);
    conv1_kernel<<<16 * NPIX, FEATC>>>(w2, b2);
    bwd_sample_kernel<<<16 * NPIX, FEATC>>>(u_roll, v_roll);
    gemm_kernel<<<dim3(57, 57, 8), 256>>>();
    rowstats_kernel<<<4 * NPIX, 256>>>();
    colstats_kernel<<<dim3(15, 4, SEG), 256>>>();
    colmerge_kernel<<<(4 * NPIX + 255) / 256, 256>>>();
    spart_kernel<<<dim3(15, 4, SEG), 256>>>();
    final_kernel<<<1, 256>>>(out);
}

// round 2
// speedup vs baseline: 1.1661x; 1.1661x over previous
#include <cuda_runtime.h>
#include <cuda_fp16.h>
#include <stdint.h>

#define HW    60
#define NPIX  3600
#define HIDC  64
#define FEATC 128
#define MSIZE (3600LL*3600LL)
#define SEG   8
#define SEGN  450   /* 3600/8 */

// ---------------- static device scratch (no allocations allowed) ----------------
__device__ float g_thetaA[16*6];
__device__ float g_thetaB[16*6];
__device__ float g_xw[16*3*NPIX];            // forward-warped inputs
__device__ float g_h1[16*HIDC*NPIX];         // conv3x3+relu
__device__ float g_y [16L*NPIX*FEATC];       // conv1x1, pixel-major [ib][p][d]
__device__ __half g_Fh[16L*NPIX*FEATC];      // features hi (fp16)
__device__ __half g_Fl[16L*NPIX*FEATC];      // features lo (fp16 residual)
__device__ float g_M [8L*3600*3600];         // [mat*4+b][n][m]; mat0=Mh, mat1=Mv  (~415MB)
__device__ float g_hmax[4*NPIX], g_hs[4*NPIX];
__device__ float g_vmax[4*NPIX], g_vs[4*NPIX];
__device__ float g_vmax_part[SEG*4*NPIX], g_vsum_part[SEG*4*NPIX];
__device__ float g_Spart[SEG*4*NPIX];

// Fast exp on the FMA pipe (no MUFU). rel err ~2e-5.
__device__ __forceinline__ float fexp(float x) {
    float t = x * 1.4426950408889634f;        // log2(e)
    t = fmaxf(t, -125.0f);                    // underflow clamp
    float r = floorf(t);
    float f = t - r;                          // [0,1)
    float p = 1.5403530e-4f;
    p = fmaf(p, f, 1.3333558e-3f);
    p = fmaf(p, f, 9.6181291e-3f);
    p = fmaf(p, f, 5.5504109e-2f);
    p = fmaf(p, f, 2.4022651e-1f);
    p = fmaf(p, f, 6.9314718e-1f);
    p = fmaf(p, f, 1.0f);
    int ei = (int)r;
    return __int_as_float((ei + 127) << 23) * p;
}

// ---------------- K0: per (inst,b) affine matrices ----------------
__global__ void theta_kernel(const float* __restrict__ noise, const int* __restrict__ swap) {
    int t = threadIdx.x;
    if (t >= 16) return;
    int i = t >> 2;
    const float* nz = noise + t * 9;
    float a  = 1.f + 0.05f * nz[0], b = 0.05f * nz[1], c = 0.05f * nz[2];
    float d  = 0.05f * nz[3], e = 1.f + 0.05f * nz[4], f = 0.05f * nz[5];
    float id = 1.f / (a * e - b * d);
    float fwd[6] = {a, b, c, d, e, f};
    float bwd[6] = { e * id, -b * id, (b * f - c * e) * id,
                    -d * id,  a * id, (c * d - a * f) * id};
    bool s = (swap[i] == 1);
#pragma unroll
    for (int k = 0; k < 6; k++) {
        g_thetaA[t * 6 + k] = s ? bwd[k] : fwd[k];
        g_thetaB[t * 6 + k] = s ? fwd[k] : bwd[k];
    }
}

// ---------------- K1: forward grid_sample with fused roll ----------------
__global__ void fwd_sample_kernel(const float* __restrict__ inA, const float* __restrict__ inB,
                                  const int* __restrict__ u_roll, const int* __restrict__ v_roll) {
    int idx = blockIdx.x * blockDim.x + threadIdx.x;
    if (idx >= 16 * 3 * NPIX) return;
    int p  = idx % NPIX;
    int c  = (idx / NPIX) % 3;
    int ib = idx / (3 * NPIX);
    int i  = ib >> 2, b = ib & 3;
    const float* T = g_thetaA + ib * 6;
    int r = p / HW, cc = p % HW;
    float xn = (2 * cc + 1) * (1.f / HW) - 1.f;
    float yn = (2 * r  + 1) * (1.f / HW) - 1.f;
    float gx = T[0] * xn + T[1] * yn + T[2];
    float gy = T[3] * xn + T[4] * yn + T[5];
    float x = (gx + 1.f) * (HW * 0.5f) - 0.5f;
    float y = (gy + 1.f) * (HW * 0.5f) - 0.5f;
    float x0f = floorf(x), y0f = floorf(y);
    int x0 = (int)x0f, y0 = (int)y0f;
    float wx1 = x - x0f, wx0 = 1.f - wx1;
    float wy1 = y - y0f, wy0 = 1.f - wy1;
    const float* src = ((i & 1) == 0) ? inA : inB;
    src += (b * 3 + c) * NPIX;
    int u = u_roll[ib], v = v_roll[ib];
    float acc = 0.f;
#pragma unroll
    for (int ky = 0; ky < 2; ky++) {
        int iy = y0 + ky;
        if (iy < 0 || iy >= HW) continue;
        int ry = iy + u; if (ry >= HW) ry -= HW;
        float wy = ky ? wy1 : wy0;
#pragma unroll
        for (int kx = 0; kx < 2; kx++) {
            int ix = x0 + kx;
            if (ix < 0 || ix >= HW) continue;
            int rx = ix + v; if (rx >= HW) rx -= HW;
            acc += wy * (kx ? wx1 : wx0) * src[ry * HW + rx];
        }
    }
    g_xw[ib * 3 * NPIX + c * NPIX + p] = acc;
}

// ---------------- K2: conv3x3 (3->64) + relu ----------------
__global__ void conv3_kernel(const float* __restrict__ w1, const float* __restrict__ b1) {
    int idx = blockIdx.x * blockDim.x + threadIdx.x;
    if (idx >= 16 * HIDC * NPIX) return;
    int p  = idx % NPIX;
    int oc = (idx / NPIX) % HIDC;
    int ib = idx / (NPIX * HIDC);
    int r = p / HW, c = p % HW;
    const float* xin = g_xw + ib * 3 * NPIX;
    const float* wk  = w1 + oc * 27;
    float acc = b1[oc];
#pragma unroll
    for (int ci = 0; ci < 3; ci++)
#pragma unroll
        for (int dy = -1; dy <= 1; dy++) {
            int rr = r + dy;
            if (rr < 0 || rr >= HW) continue;
#pragma unroll
            for (int dx = -1; dx <= 1; dx++) {
                int c2 = c + dx;
                if (c2 < 0 || c2 >= HW) continue;
                acc += wk[ci * 9 + (dy + 1) * 3 + (dx + 1)] * xin[ci * NPIX + rr * HW + c2];
            }
        }
    g_h1[(ib * HIDC + oc) * NPIX + p] = fmaxf(acc, 0.f);
}

// ---------------- K3: conv1x1 (64->128) + bias ----------------
__global__ void conv1_kernel(const float* __restrict__ w2, const float* __restrict__ b2) {
    int blk = blockIdx.x;
    int ib = blk / NPIX, p = blk % NPIX;
    int d  = threadIdx.x;
    __shared__ float sh[HIDC];
    if (d < HIDC) sh[d] = g_h1[(ib * HIDC + d) * NPIX + p];
    __syncthreads();
    const float* wr = w2 + d * HIDC;
    float acc = b2[d];
#pragma unroll
    for (int h = 0; h < HIDC; h++) acc = fmaf(wr[h], sh[h], acc);
    g_y[((size_t)ib * NPIX + p) * FEATC + d] = acc;
}

// ---------------- K4: backward grid_sample (128ch), writes fp16 hi/lo split ----------------
__global__ void bwd_sample_kernel(const int* __restrict__ u_roll, const int* __restrict__ v_roll) {
    int blk = blockIdx.x;
    int ib = blk / NPIX, n = blk % NPIX;
    int d  = threadIdx.x;
    __shared__ float wt[4];
    __shared__ int   pp[4];
    if (d == 0) {
        int u = u_roll[ib], v = v_roll[ib];
        int r = n / HW, c = n % HW;
        int rr = r - u; if (rr < 0) rr += HW;
        int cc = c - v; if (cc < 0) cc += HW;
        const float* T = g_thetaB + ib * 6;
        float xn = (2 * cc + 1) * (1.f / HW) - 1.f;
        float yn = (2 * rr + 1) * (1.f / HW) - 1.f;
        float gx = T[0] * xn + T[1] * yn + T[2];
        float gy = T[3] * xn + T[4] * yn + T[5];
        float x = (gx + 1.f) * (HW * 0.5f) - 0.5f;
        float y = (gy + 1.f) * (HW * 0.5f) - 0.5f;
        float x0f = floorf(x), y0f = floorf(y);
        int x0 = (int)x0f, y0 = (int)y0f;
        float wx1 = x - x0f, wx0 = 1.f - wx1;
        float wy1 = y - y0f, wy0 = 1.f - wy1;
#pragma unroll
        for (int k = 0; k < 4; k++) {
            int iy = y0 + (k >> 1), ix = x0 + (k & 1);
            bool ok = (iy >= 0 && iy < HW && ix >= 0 && ix < HW);
            pp[k] = ok ? (iy * HW + ix) : -1;
            wt[k] = ((k >> 1) ? wy1 : wy0) * ((k & 1) ? wx1 : wx0);
        }
    }
    __syncthreads();
    const float* yb = g_y + (size_t)ib * NPIX * FEATC;
    float acc = 0.f;
#pragma unroll
    for (int k = 0; k < 4; k++) {
        int q = pp[k];
        if (q >= 0) acc += wt[k] * yb[(size_t)q * FEATC + d];
    }
    size_t o = ((size_t)ib * NPIX + n) * FEATC + d;
    __half h = __float2half_rn(acc);
    g_Fh[o] = h;
    g_Fl[o] = __float2half_rn(acc - __half2float(h));
}

// ---------------- K5: split-fp16 HMMA GEMM, 128x128 tiles, K=128 ----------------
// smem layout (u32 units), fragment order:
//   A: [prec][kt(8)][mt(8)][lane(32)][4]  = 16384 u32 (64KB)
//   B: [prec][kt(8)][nt(16)][lane(32)][2] = 16384 u32 (64KB)
#define A_IDX(p,kt,mt,lane,r) (((((p)*8+(kt))*8+(mt))*32+(lane))*4+(r))
#define B_IDX(p,kt,nt,lane,r) (16384 + ((((p)*8+(kt))*16+(nt))*32+(lane))*2+(r))

#define HMMA16816(D, A0, A1, A2, A3, B0, B1)                                     \
    asm volatile("mma.sync.aligned.m16n8k16.row.col.f32.f16.f16.f32 "            \
                 "{%0,%1,%2,%3}, {%4,%5,%6,%7}, {%8,%9}, {%0,%1,%2,%3};\n"       \
                 : "+f"(D[0]), "+f"(D[1]), "+f"(D[2]), "+f"(D[3])                \
                 : "r"(A0), "r"(A1), "r"(A2), "r"(A3), "r"(B0), "r"(B1))

__global__ __launch_bounds__(256, 1) void gemm_mma_kernel() {
    extern __shared__ uint32_t smem[];
    int z = blockIdx.z;                       // mat*4 + b
    int mat = z >> 2, b = z & 3;
    size_t baseA = (size_t)((mat * 2)     * 4 + b) * NPIX * FEATC;
    size_t baseB = (size_t)((mat * 2 + 1) * 4 + b) * NPIX * FEATC;
    const uint32_t* Ah = (const uint32_t*)(g_Fh + baseA);   // 64 u32 per row
    const uint32_t* Al = (const uint32_t*)(g_Fl + baseA);
    const uint32_t* Bh = (const uint32_t*)(g_Fh + baseB);
    const uint32_t* Bl = (const uint32_t*)(g_Fl + baseB);
    float* C = g_M + (size_t)z * MSIZE;
    int n0 = blockIdx.y * 128, m0 = blockIdx.x * 128;
    int tid = threadIdx.x;

    // ---- copy A into fragment order ----
#pragma unroll
    for (int i = 0; i < 16; i++) {
        int slot = tid + i * 256;
        int lane = slot & 31;
        int rest = slot >> 5;
        int mt = rest & 7, kt = (rest >> 3) & 7, p = rest >> 6;
        int g = lane >> 2, t4 = lane & 3;
        int r0 = n0 + mt * 16 + g, r1 = r0 + 8;
        int c0 = kt * 8 + t4, c1 = c0 + 4;
        const uint32_t* src = p ? Al : Ah;
        uint4 v;
        v.x = (r0 < NPIX) ? src[r0 * 64 + c0] : 0u;
        v.y = (r1 < NPIX) ? src[r1 * 64 + c0] : 0u;
        v.z = (r0 < NPIX) ? src[r0 * 64 + c1] : 0u;
        v.w = (r1 < NPIX) ? src[r1 * 64 + c1] : 0u;
        *(uint4*)&smem[A_IDX(p, kt, mt, lane, 0)] = v;
    }
    // ---- copy B into fragment order ----
#pragma unroll
    for (int i = 0; i < 32; i++) {
        int slot = tid + i * 256;
        int lane = slot & 31;
        int rest = slot >> 5;
        int nt = rest & 15, kt = (rest >> 4) & 7, p = rest >> 7;
        int g = lane >> 2, t4 = lane & 3;
        int m = m0 + nt * 8 + g;
        int c0 = kt * 8 + t4, c1 = c0 + 4;
        const uint32_t* src = p ? Bl : Bh;
        uint2 v;
        v.x = (m < NPIX) ? src[m * 64 + c0] : 0u;
        v.y = (m < NPIX) ? src[m * 64 + c1] : 0u;
        *(uint2*)&smem[B_IDX(p, kt, nt, lane, 0)] = v;
    }
    __syncthreads();

    int wid = tid >> 5, lane = tid & 31;
    int wr = wid >> 1, wc = wid & 1;          // warp tile: rows wr*32 (2 mt), cols wc*64 (8 nt)

    float acc[2][8][4];
#pragma unroll
    for (int a = 0; a < 2; a++)
#pragma unroll
        for (int nn = 0; nn < 8; nn++)
#pragma unroll
            for (int r = 0; r < 4; r++) acc[a][nn][r] = 0.f;

#pragma unroll
    for (int kt = 0; kt < 8; kt++) {
        uint32_t afr[2][2][4];                // [mt2][prec][4]
#pragma unroll
        for (int mt2 = 0; mt2 < 2; mt2++) {
            int mt = wr * 2 + mt2;
            *(uint4*)afr[mt2][0] = *(const uint4*)&smem[A_IDX(0, kt, mt, lane, 0)];
            *(uint4*)afr[mt2][1] = *(const uint4*)&smem[A_IDX(1, kt, mt, lane, 0)];
        }
        uint32_t bfr[8][2][2];                // [nt2][prec][2]
#pragma unroll
        for (int nt2 = 0; nt2 < 8; nt2++) {
            int nt = wc * 8 + nt2;
            *(uint2*)bfr[nt2][0] = *(const uint2*)&smem[B_IDX(0, kt, nt, lane, 0)];
            *(uint2*)bfr[nt2][1] = *(const uint2*)&smem[B_IDX(1, kt, nt, lane, 0)];
        }
#pragma unroll
        for (int mt2 = 0; mt2 < 2; mt2++)
#pragma unroll
            for (int nt2 = 0; nt2 < 8; nt2++) {
                HMMA16816(acc[mt2][nt2], afr[mt2][0][0], afr[mt2][0][1], afr[mt2][0][2], afr[mt2][0][3],
                          bfr[nt2][0][0], bfr[nt2][0][1]);                 // hi*hi
                HMMA16816(acc[mt2][nt2], afr[mt2][0][0], afr[mt2][0][1], afr[mt2][0][2], afr[mt2][0][3],
                          bfr[nt2][1][0], bfr[nt2][1][1]);                 // hi*lo
                HMMA16816(acc[mt2][nt2], afr[mt2][1][0], afr[mt2][1][1], afr[mt2][1][2], afr[mt2][1][3],
                          bfr[nt2][0][0], bfr[nt2][0][1]);                 // lo*hi
            }
    }

    // ---- store C ----
    int g = lane >> 2, t4 = lane & 3;
#pragma unroll
    for (int mt2 = 0; mt2 < 2; mt2++) {
        int rbase = n0 + (wr * 2 + mt2) * 16 + g;
#pragma unroll
        for (int nt2 = 0; nt2 < 8; nt2++) {
            int col = m0 + (wc * 8 + nt2) * 8 + 2 * t4;
            if (col < NPIX) {
                if (rbase < NPIX)
                    *(float2*)&C[(size_t)rbase * NPIX + col] = make_float2(acc[mt2][nt2][0], acc[mt2][nt2][1]);
                if (rbase + 8 < NPIX)
                    *(float2*)&C[(size_t)(rbase + 8) * NPIX + col] = make_float2(acc[mt2][nt2][2], acc[mt2][nt2][3]);
            }
        }
    }
}

// ---------------- K6: Mh row stats, single-pass online softmax ----------------
__global__ void rowstats_kernel() {
    int blk = blockIdx.x;                     // b*3600 + n
    int b = blk / NPIX, n = blk % NPIX;
    const float* row = g_M + (size_t)b * MSIZE + (size_t)n * NPIX;
    __shared__ float redm[256], reds[256];
    int t = threadIdx.x;
    float mx = -1e30f, s = 0.f;
    for (int m = t; m < NPIX; m += 256) {
        float x = row[m];
        if (x > mx) { s = s * fexp(mx - x) + 1.f; mx = x; }
        else          s += fexp(x - mx);
    }
    redm[t] = mx; reds[t] = s; __syncthreads();
    for (int st = 128; st > 0; st >>= 1) {
        if (t < st) {
            float m1 = redm[t], m2 = redm[t + st];
            float M = fmaxf(m1, m2);
            reds[t] = reds[t] * fexp(m1 - M) + reds[t + st] * fexp(m2 - M);
            redm[t] = M;
        }
        __syncthreads();
    }
    if (t == 0) { g_hmax[blk] = redm[0]; g_hs[blk] = 1.f / (reds[0] + 1e-4f); }
}

// ---------------- K7a: Mv column stats, per-segment online ----------------
__global__ void colstats_kernel() {
    int m = blockIdx.x * 256 + threadIdx.x;
    int b = blockIdx.y, seg = blockIdx.z;
    if (m >= NPIX) return;
    const float* Mv = g_M + (size_t)(4 + b) * MSIZE;
    float mx = -1e30f, s = 0.f;
    int n0 = seg * SEGN, n1 = n0 + SEGN;
    for (int n = n0; n < n1; n++) {
        float x = Mv[(size_t)n * NPIX + m];
        if (x > mx) { s = s * fexp(mx - x) + 1.f; mx = x; }
        else         s += fexp(x - mx);
    }
    g_vmax_part[(seg * 4 + b) * NPIX + m] = mx;
    g_vsum_part[(seg * 4 + b) * NPIX + m] = s;
}

// ---------------- K7b: merge column-stat segments ----------------
__global__ void colmerge_kernel() {
    int idx = blockIdx.x * blockDim.x + threadIdx.x;
    if (idx >= 4 * NPIX) return;
    int b = idx / NPIX, m = idx % NPIX;
    float mx = -1e30f, s = 0.f;
#pragma unroll
    for (int seg = 0; seg < SEG; seg++) {
        float pm = g_vmax_part[(seg * 4 + b) * NPIX + m];
        float ps = g_vsum_part[(seg * 4 + b) * NPIX + m];
        if (pm > mx) { s = s * fexp(mx - pm) + ps; mx = pm; }
        else           s += ps * fexp(pm - mx);
    }
    g_vmax[idx] = mx;
    g_vs[idx]   = 1.f / (s + 1e-4f);
}

// ---------------- K8: S[b,m] partial sums over n segments ----------------
__global__ void spart_kernel() {
    int m = blockIdx.x * 256 + threadIdx.x;
    int b = blockIdx.y, seg = blockIdx.z;
    if (m >= NPIX) return;
    const float* Mh = g_M + (size_t)b * MSIZE;
    const float* Mv = g_M + (size_t)(4 + b) * MSIZE;
    float vmaxm = g_vmax[b * NPIX + m];
    float s = 0.f;
    int n0 = seg * SEGN, n1 = n0 + SEGN;
    for (int n = n0; n < n1; n++) {
        float e = fexp(Mv[(size_t)n * NPIX + m] - vmaxm + Mh[(size_t)n * NPIX + m] - g_hmax[b * NPIX + n]);
        s = fmaf(e, g_hs[b * NPIX + n], s);
    }
    g_Spart[(seg * 4 + b) * NPIX + m] = s;
}

// ---------------- K9: deterministic final reduction ----------------
__global__ void final_kernel(float* __restrict__ out) {
    __shared__ float red[256];
    int t = threadIdx.x;
    float acc = 0.f;
    for (int idx = t; idx < 4 * NPIX; idx += 256) {
        int b = idx / NPIX, m = idx % NPIX;
        float S = 0.f;
#pragma unroll
        for (int seg = 0; seg < SEG; seg++) S += g_Spart[(seg * 4 + b) * NPIX + m];
        acc += logf(S * g_vs[idx] + 1e-4f);
    }
    red[t] = acc; __syncthreads();
    for (int s = 128; s > 0; s >>= 1) { if (t < s) red[t] += red[t + s]; __syncthreads(); }
    if (t == 0) out[0] = red[0] * (1.f / (4.f * NPIX));
}

// ---------------- launch ----------------
extern "C" void kernel_launch(void* const* d_in, const int* in_sizes, int n_in,
                              void* d_out, int out_size) {
    const float* input_a = (const float*)d_in[0];
    const float* input_b = (const float*)d_in[1];
    const float* w1      = (const float*)d_in[2];
    const float* b1      = (const float*)d_in[3];
    const float* w2      = (const float*)d_in[4];
    const float* b2      = (const float*)d_in[5];
    const float* noise   = (const float*)d_in[6];
    const int*   u_roll  = (const int*)d_in[7];
    const int*   v_roll  = (const int*)d_in[8];
    const int*   swap    = (const int*)d_in[9];
    float* out = (float*)d_out;

    cudaFuncSetAttribute(gemm_mma_kernel, cudaFuncAttributeMaxDynamicSharedMemorySize, 131072);

    theta_kernel<<<1, 32>>>(noise, swap);
    fwd_sample_kernel<<<(16 * 3 * NPIX + 255) / 256, 256>>>(input_a, input_b, u_roll, v_roll);
    conv3_kernel<<<(16 * HIDC * NPIX + 255) / 256, 256>>>(w1, b1);
    conv1_kernel<<<16 * NPIX, FEATC>>>(w2, b2);
    bwd_sample_kernel<<<16 * NPIX, FEATC>>>(u_roll, v_roll);
    gemm_mma_kernel<<<dim3(29, 29, 8), 256, 131072>>>();
    rowstats_kernel<<<4 * NPIX, 256>>>();
    colstats_kernel<<<dim3(15, 4, SEG), 256>>>();
    colmerge_kernel<<<(4 * NPIX + 255) / 256, 256>>>();
    spart_kernel<<<dim3(15, 4, SEG), 256>>>();
    final_kernel<<<1, 256>>>(out);
}

// round 4
// speedup vs baseline: 1.2696x; 1.0888x over previous
#include <cuda_runtime.h>
#include <cuda_fp16.h>
#include <stdint.h>

#define HW    60
#define NPIX  3600
#define HIDC  64
#define FEATC 128
#define MSIZE (3600LL*3600LL)
#define SEG   8
#define SEGN  450   /* 3600/8 */

// ---------------- static device scratch (no allocations allowed) ----------------
__device__ float g_xw[16*3*NPIX];            // forward-warped inputs
__device__ float g_h1[16*HIDC*NPIX];         // conv3x3+relu
__device__ __half g_Fh[16L*NPIX*FEATC];      // features hi (fp16)
__device__ __half g_Fl[16L*NPIX*FEATC];      // features lo (fp16 residual)
__device__ float g_M [8L*3600*3600];         // [mat*4+b][n][m]; mat0=Mh, mat1=Mv  (~415MB)
__device__ float g_hmax[4*NPIX], g_hs[4*NPIX];
__device__ float g_vmax[4*NPIX], g_vs[4*NPIX];
__device__ float g_vmax_part[SEG*4*NPIX], g_vsum_part[SEG*4*NPIX];
__device__ float g_Spart[SEG*4*NPIX];

// Fast exp on the FMA pipe (no MUFU). rel err ~2e-5.
__device__ __forceinline__ float fexp(float x) {
    float t = x * 1.4426950408889634f;
    t = fmaxf(t, -125.0f);
    float r = floorf(t);
    float f = t - r;
    float p = 1.5403530e-4f;
    p = fmaf(p, f, 1.3333558e-3f);
    p = fmaf(p, f, 9.6181291e-3f);
    p = fmaf(p, f, 5.5504109e-2f);
    p = fmaf(p, f, 2.4022651e-1f);
    p = fmaf(p, f, 6.9314718e-1f);
    p = fmaf(p, f, 1.0f);
    int ei = (int)r;
    return __int_as_float((ei + 127) << 23) * p;
}

// theta for instance-batch ib: fills A (forward-or-inverse per swap) and/or B.
__device__ __forceinline__ void compute_theta(const float* __restrict__ noise, int swp, int ib,
                                              float* TA, float* TB) {
    const float* nz = noise + ib * 9;
    float a  = 1.f + 0.05f * nz[0], b = 0.05f * nz[1], c = 0.05f * nz[2];
    float d  = 0.05f * nz[3], e = 1.f + 0.05f * nz[4], f = 0.05f * nz[5];
    float id = 1.f / (a * e - b * d);
    float fwd[6] = {a, b, c, d, e, f};
    float bwd[6] = { e * id, -b * id, (b * f - c * e) * id,
                    -d * id,  a * id, (c * d - a * f) * id};
    bool s = (swp == 1);
#pragma unroll
    for (int k = 0; k < 6; k++) {
        if (TA) TA[k] = s ? bwd[k] : fwd[k];
        if (TB) TB[k] = s ? fwd[k] : bwd[k];
    }
}

// ---------------- K1: forward grid_sample with fused roll + inline theta ----------------
__global__ void fwd_sample_kernel(const float* __restrict__ inA, const float* __restrict__ inB,
                                  const float* __restrict__ noise, const int* __restrict__ swap,
                                  const int* __restrict__ u_roll, const int* __restrict__ v_roll) {
    int idx = blockIdx.x * blockDim.x + threadIdx.x;
    if (idx >= 16 * 3 * NPIX) return;
    int p  = idx % NPIX;
    int c  = (idx / NPIX) % 3;
    int ib = idx / (3 * NPIX);
    int i  = ib >> 2, b = ib & 3;
    float T[6];
    compute_theta(noise, swap[i], ib, T, nullptr);
    int r = p / HW, cc = p % HW;
    float xn = (2 * cc + 1) * (1.f / HW) - 1.f;
    float yn = (2 * r  + 1) * (1.f / HW) - 1.f;
    float gx = T[0] * xn + T[1] * yn + T[2];
    float gy = T[3] * xn + T[4] * yn + T[5];
    float x = (gx + 1.f) * (HW * 0.5f) - 0.5f;
    float y = (gy + 1.f) * (HW * 0.5f) - 0.5f;
    float x0f = floorf(x), y0f = floorf(y);
    int x0 = (int)x0f, y0 = (int)y0f;
    float wx1 = x - x0f, wx0 = 1.f - wx1;
    float wy1 = y - y0f, wy0 = 1.f - wy1;
    const float* src = ((i & 1) == 0) ? inA : inB;
    src += (b * 3 + c) * NPIX;
    int u = u_roll[ib], v = v_roll[ib];
    float acc = 0.f;
#pragma unroll
    for (int ky = 0; ky < 2; ky++) {
        int iy = y0 + ky;
        if (iy < 0 || iy >= HW) continue;
        int ry = iy + u; if (ry >= HW) ry -= HW;
        float wy = ky ? wy1 : wy0;
#pragma unroll
        for (int kx = 0; kx < 2; kx++) {
            int ix = x0 + kx;
            if (ix < 0 || ix >= HW) continue;
            int rx = ix + v; if (rx >= HW) rx -= HW;
            acc += wy * (kx ? wx1 : wx0) * src[ry * HW + rx];
        }
    }
    g_xw[ib * 3 * NPIX + c * NPIX + p] = acc;
}

// ---------------- K2: conv3x3 (3->64) + relu ----------------
__global__ void conv3_kernel(const float* __restrict__ w1, const float* __restrict__ b1) {
    int idx = blockIdx.x * blockDim.x + threadIdx.x;
    if (idx >= 16 * HIDC * NPIX) return;
    int p  = idx % NPIX;
    int oc = (idx / NPIX) % HIDC;
    int ib = idx / (NPIX * HIDC);
    int r = p / HW, c = p % HW;
    const float* xin = g_xw + ib * 3 * NPIX;
    const float* wk  = w1 + oc * 27;
    float acc = b1[oc];
#pragma unroll
    for (int ci = 0; ci < 3; ci++)
#pragma unroll
        for (int dy = -1; dy <= 1; dy++) {
            int rr = r + dy;
            if (rr < 0 || rr >= HW) continue;
#pragma unroll
            for (int dx = -1; dx <= 1; dx++) {
                int c2 = c + dx;
                if (c2 < 0 || c2 >= HW) continue;
                acc += wk[ci * 9 + (dy + 1) * 3 + (dx + 1)] * xin[ci * NPIX + rr * HW + c2];
            }
        }
    g_h1[(ib * HIDC + oc) * NPIX + p] = fmaxf(acc, 0.f);
}

// ---------------- K3: fused backward grid_sample + conv1x1 ----------------
// F[n] = W2 * (sum_k wt_k h1[q_k]) + wsum*b2   (linearity; zero-padding -> wsum)
__global__ void bwdconv1_kernel(const float* __restrict__ w2, const float* __restrict__ b2,
                                const float* __restrict__ noise, const int* __restrict__ swap,
                                const int* __restrict__ u_roll, const int* __restrict__ v_roll) {
    int blk = blockIdx.x;
    int ib = blk / NPIX, n = blk % NPIX;
    int d  = threadIdx.x;
    __shared__ float wt[4];
    __shared__ int   pp[4];
    __shared__ float sh_h[HIDC];
    __shared__ float sh_ws;
    if (d == 0) {
        float T[6];
        compute_theta(noise, swap[ib >> 2], ib, nullptr, T);
        int u = u_roll[ib], v = v_roll[ib];
        int r = n / HW, c = n % HW;
        int rr = r - u; if (rr < 0) rr += HW;
        int cc = c - v; if (cc < 0) cc += HW;
        float xn = (2 * cc + 1) * (1.f / HW) - 1.f;
        float yn = (2 * rr + 1) * (1.f / HW) - 1.f;
        float gx = T[0] * xn + T[1] * yn + T[2];
        float gy = T[3] * xn + T[4] * yn + T[5];
        float x = (gx + 1.f) * (HW * 0.5f) - 0.5f;
        float y = (gy + 1.f) * (HW * 0.5f) - 0.5f;
        float x0f = floorf(x), y0f = floorf(y);
        int x0 = (int)x0f, y0 = (int)y0f;
        float wx1 = x - x0f, wx0 = 1.f - wx1;
        float wy1 = y - y0f, wy0 = 1.f - wy1;
        float ws = 0.f;
#pragma unroll
        for (int k = 0; k < 4; k++) {
            int iy = y0 + (k >> 1), ix = x0 + (k & 1);
            bool ok = (iy >= 0 && iy < HW && ix >= 0 && ix < HW);
            pp[k] = ok ? (iy * HW + ix) : -1;
            wt[k] = ((k >> 1) ? wy1 : wy0) * ((k & 1) ? wx1 : wx0);
            if (ok) ws += wt[k];
        }
        sh_ws = ws;
    }
    __syncthreads();
    if (d < HIDC) {
        const float* hb = g_h1 + (size_t)(ib * HIDC + d) * NPIX;
        float a = 0.f;
#pragma unroll
        for (int k = 0; k < 4; k++) {
            int q = pp[k];
            if (q >= 0) a += wt[k] * hb[q];
        }
        sh_h[d] = a;
    }
    __syncthreads();
    const float* wr = w2 + d * HIDC;
    float acc = sh_ws * b2[d];
#pragma unroll
    for (int h = 0; h < HIDC; h++) acc = fmaf(wr[h], sh_h[h], acc);
    size_t o = ((size_t)ib * NPIX + n) * FEATC + d;
    __half hv = __float2half_rn(acc);
    g_Fh[o] = hv;
    g_Fl[o] = __float2half_rn(acc - __half2float(hv));
}

// ---------------- K4: split-fp16 HMMA GEMM, 128x128 tile, ldmatrix + swizzle ----------------
// smem (bytes): A_hi [0,32768), A_lo [32768,65536), B(phase) [65536,98304)
#define SA_HI 0
#define SA_LO 32768
#define SB_OFF 65536
#define GEMM_SMEM 98304
// row r (0..127) of 256B (16 x 16B chunks); xor-swizzle chunk low bits by row
__device__ __forceinline__ uint32_t sw_off(int r, int c16) {
    return (uint32_t)(r * 256 + ((((c16 ^ r) & 7)) | (c16 & 8)) * 16);
}
__device__ __forceinline__ uint32_t smem_u32(const void* p) {
    uint32_t a;
    asm("{ .reg .u64 t; cvta.to.shared.u64 t, %1; cvt.u32.u64 %0, t; }" : "=r"(a) : "l"(p));
    return a;
}
#define LDSM_X4(R0, R1, R2, R3, addr)                                             \
    asm volatile("ldmatrix.sync.aligned.m8n8.x4.shared.b16 {%0,%1,%2,%3}, [%4];"  \
                 : "=r"(R0), "=r"(R1), "=r"(R2), "=r"(R3) : "r"(addr))
#define HMMA16816(D, A0, A1, A2, A3, B0, B1)                                      \
    asm volatile("mma.sync.aligned.m16n8k16.row.col.f32.f16.f16.f32 "             \
                 "{%0,%1,%2,%3}, {%4,%5,%6,%7}, {%8,%9}, {%0,%1,%2,%3};\n"        \
                 : "+f"(D[0]), "+f"(D[1]), "+f"(D[2]), "+f"(D[3])                 \
                 : "r"(A0), "r"(A1), "r"(A2), "r"(A3), "r"(B0), "r"(B1))

__global__ __launch_bounds__(256, 2) void gemm_hmma_kernel() {
    extern __shared__ char smem[];
    uint32_t sb = smem_u32(smem);
    int z = blockIdx.z;                       // mat*4 + b
    int mat = z >> 2, b = z & 3;
    size_t baseA = (size_t)((mat * 2)     * 4 + b) * NPIX * FEATC;
    size_t baseB = (size_t)((mat * 2 + 1) * 4 + b) * NPIX * FEATC;
    float* C = g_M + (size_t)z * MSIZE;
    int n0 = blockIdx.y * 128, m0 = blockIdx.x * 128;
    int tid = threadIdx.x;
    int wid = tid >> 5, lane = tid & 31;
    int wr = wid >> 2, wc = wid & 3;          // warp: rows wr*64(4 mt), cols wc*32(4 nt)

    // ---- copy A hi+lo (4096 uint4, coalesced) ----
    {
        const uint4* srcH = (const uint4*)(g_Fh + baseA);
        const uint4* srcL = (const uint4*)(g_Fl + baseA);
#pragma unroll
        for (int i = 0; i < 16; i++) {
            int slot = tid + i * 256;
            int c16 = slot & 15, row = (slot >> 4) & 127, p = slot >> 11;
            int gr = n0 + row;
            uint4 v = make_uint4(0, 0, 0, 0);
            if (gr < NPIX) v = (p ? srcL : srcH)[gr * 16 + c16];
            *(uint4*)(smem + (p ? SA_LO : SA_HI) + sw_off(row, c16)) = v;
        }
    }
    // ---- copy B hi (2048 uint4) ----
    {
        const uint4* srcH = (const uint4*)(g_Fh + baseB);
#pragma unroll
        for (int i = 0; i < 8; i++) {
            int slot = tid + i * 256;
            int c16 = slot & 15, row = slot >> 4;
            int gm = m0 + row;
            uint4 v = make_uint4(0, 0, 0, 0);
            if (gm < NPIX) v = srcH[gm * 16 + c16];
            *(uint4*)(smem + SB_OFF + sw_off(row, c16)) = v;
        }
    }
    __syncthreads();

    float acc[4][4][4];
#pragma unroll
    for (int u = 0; u < 4; u++)
#pragma unroll
        for (int v = 0; v < 4; v++)
#pragma unroll
            for (int r = 0; r < 4; r++) acc[u][v][r] = 0.f;

    // lane-dependent ldmatrix address components
    int a_row_l = ((lane >> 3) & 1) * 8 + (lane & 7);   // + mt*16 + wr*64
    int a_c16_l = (lane >> 4);                          // + 2*kt
    int b_row_l = ((lane >> 4) * 8) + (lane & 7);       // + np*16 + wc*32
    int b_c16_l = ((lane >> 3) & 1);                    // + 2*kt

    // ---- phase 1: B=hi, terms hi*hi + lo*hi ----
#pragma unroll
    for (int kt = 0; kt < 8; kt++) {
        uint32_t ah[4][4], al[4][4], bf[4][2];
#pragma unroll
        for (int mt = 0; mt < 4; mt++) {
            uint32_t off = sw_off(wr * 64 + mt * 16 + a_row_l, 2 * kt + a_c16_l);
            LDSM_X4(ah[mt][0], ah[mt][1], ah[mt][2], ah[mt][3], sb + SA_HI + off);
            LDSM_X4(al[mt][0], al[mt][1], al[mt][2], al[mt][3], sb + SA_LO + off);
        }
#pragma unroll
        for (int np = 0; np < 2; np++) {
            uint32_t off = sw_off(wc * 32 + np * 16 + b_row_l, 2 * kt + b_c16_l);
            LDSM_X4(bf[np * 2][0], bf[np * 2][1], bf[np * 2 + 1][0], bf[np * 2 + 1][1], sb + SB_OFF + off);
        }
#pragma unroll
        for (int mt = 0; mt < 4; mt++)
#pragma unroll
            for (int nt = 0; nt < 4; nt++) {
                HMMA16816(acc[mt][nt], ah[mt][0], ah[mt][1], ah[mt][2], ah[mt][3], bf[nt][0], bf[nt][1]);
                HMMA16816(acc[mt][nt], al[mt][0], al[mt][1], al[mt][2], al[mt][3], bf[nt][0], bf[nt][1]);
            }
    }
    __syncthreads();

    // ---- copy B lo ----
    {
        const uint4* srcL = (const uint4*)(g_Fl + baseB);
#pragma unroll
        for (int i = 0; i < 8; i++) {
            int slot = tid + i * 256;
            int c16 = slot & 15, row = slot >> 4;
            int gm = m0 + row;
            uint4 v = make_uint4(0, 0, 0, 0);
            if (gm < NPIX) v = srcL[gm * 16 + c16];
            *(uint4*)(smem + SB_OFF + sw_off(row, c16)) = v;
        }
    }
    __syncthreads();

    // ---- phase 2: B=lo, term hi*lo ----
#pragma unroll
    for (int kt = 0; kt < 8; kt++) {
        uint32_t ah[4][4], bf[4][2];
#pragma unroll
        for (int mt = 0; mt < 4; mt++) {
            uint32_t off = sw_off(wr * 64 + mt * 16 + a_row_l, 2 * kt + a_c16_l);
            LDSM_X4(ah[mt][0], ah[mt][1], ah[mt][2], ah[mt][3], sb + SA_HI + off);
        }
#pragma unroll
        for (int np = 0; np < 2; np++) {
            uint32_t off = sw_off(wc * 32 + np * 16 + b_row_l, 2 * kt + b_c16_l);
            LDSM_X4(bf[np * 2][0], bf[np * 2][1], bf[np * 2 + 1][0], bf[np * 2 + 1][1], sb + SB_OFF + off);
        }
#pragma unroll
        for (int mt = 0; mt < 4; mt++)
#pragma unroll
            for (int nt = 0; nt < 4; nt++)
                HMMA16816(acc[mt][nt], ah[mt][0], ah[mt][1], ah[mt][2], ah[mt][3], bf[nt][0], bf[nt][1]);
    }

    // ---- store C ----
    int g = lane >> 2, t4 = lane & 3;
#pragma unroll
    for (int mt = 0; mt < 4; mt++) {
        int r0 = n0 + wr * 64 + mt * 16 + g;
#pragma unroll
        for (int nt = 0; nt < 4; nt++) {
            int col = m0 + wc * 32 + nt * 8 + 2 * t4;
            if (col < NPIX) {
                if (r0 < NPIX)
                    *(float2*)&C[(size_t)r0 * NPIX + col] = make_float2(acc[mt][nt][0], acc[mt][nt][1]);
                if (r0 + 8 < NPIX)
                    *(float2*)&C[(size_t)(r0 + 8) * NPIX + col] = make_float2(acc[mt][nt][2], acc[mt][nt][3]);
            }
        }
    }
}

// ---------------- K5: Mh row stats, single-pass online softmax ----------------
__global__ void rowstats_kernel() {
    int blk = blockIdx.x;                     // b*3600 + n
    int b = blk / NPIX, n = blk % NPIX;
    const float* row = g_M + (size_t)b * MSIZE + (size_t)n * NPIX;
    __shared__ float redm[256], reds[256];
    int t = threadIdx.x;
    float mx = -1e30f, s = 0.f;
    for (int m = t; m < NPIX; m += 256) {
        float x = row[m];
        if (x > mx) { s = s * fexp(mx - x) + 1.f; mx = x; }
        else          s += fexp(x - mx);
    }
    redm[t] = mx; reds[t] = s; __syncthreads();
    for (int st = 128; st > 0; st >>= 1) {
        if (t < st) {
            float m1 = redm[t], m2 = redm[t + st];
            float M = fmaxf(m1, m2);
            reds[t] = reds[t] * fexp(m1 - M) + reds[t + st] * fexp(m2 - M);
            redm[t] = M;
        }
        __syncthreads();
    }
    if (t == 0) { g_hmax[blk] = redm[0]; g_hs[blk] = 1.f / (reds[0] + 1e-4f); }
}

// ---------------- K6a: Mv column stats, per-segment online ----------------
__global__ void colstats_kernel() {
    int m = blockIdx.x * 256 + threadIdx.x;
    int b = blockIdx.y, seg = blockIdx.z;
    if (m >= NPIX) return;
    const float* Mv = g_M + (size_t)(4 + b) * MSIZE;
    float mx = -1e30f, s = 0.f;
    int n0 = seg * SEGN, n1 = n0 + SEGN;
    for (int n = n0; n < n1; n++) {
        float x = Mv[(size_t)n * NPIX + m];
        if (x > mx) { s = s * fexp(mx - x) + 1.f; mx = x; }
        else         s += fexp(x - mx);
    }
    g_vmax_part[(seg * 4 + b) * NPIX + m] = mx;
    g_vsum_part[(seg * 4 + b) * NPIX + m] = s;
}

// ---------------- K6b: merge column-stat segments ----------------
__global__ void colmerge_kernel() {
    int idx = blockIdx.x * blockDim.x + threadIdx.x;
    if (idx >= 4 * NPIX) return;
    int b = idx / NPIX, m = idx % NPIX;
    float mx = -1e30f, s = 0.f;
#pragma unroll
    for (int seg = 0; seg < SEG; seg++) {
        float pm = g_vmax_part[(seg * 4 + b) * NPIX + m];
        float ps = g_vsum_part[(seg * 4 + b) * NPIX + m];
        if (pm > mx) { s = s * fexp(mx - pm) + ps; mx = pm; }
        else           s += ps * fexp(pm - mx);
    }
    g_vmax[idx] = mx;
    g_vs[idx]   = 1.f / (s + 1e-4f);
}

// ---------------- K7: S[b,m] partial sums over n segments ----------------
__global__ void spart_kernel() {
    int m = blockIdx.x * 256 + threadIdx.x;
    int b = blockIdx.y, seg = blockIdx.z;
    if (m >= NPIX) return;
    const float* Mh = g_M + (size_t)b * MSIZE;
    const float* Mv = g_M + (size_t)(4 + b) * MSIZE;
    float vmaxm = g_vmax[b * NPIX + m];
    float s = 0.f;
    int n0 = seg * SEGN, n1 = n0 + SEGN;
    for (int n = n0; n < n1; n++) {
        float e = fexp(Mv[(size_t)n * NPIX + m] - vmaxm + Mh[(size_t)n * NPIX + m] - g_hmax[b * NPIX + n]);
        s = fmaf(e, g_hs[b * NPIX + n], s);
    }
    g_Spart[(seg * 4 + b) * NPIX + m] = s;
}

// ---------------- K8: deterministic final reduction ----------------
__global__ void final_kernel(float* __restrict__ out) {
    __shared__ float red[256];
    int t = threadIdx.x;
    float acc = 0.f;
    for (int idx = t; idx < 4 * NPIX; idx += 256) {
        int b = idx / NPIX, m = idx % NPIX;
        float S = 0.f;
#pragma unroll
        for (int seg = 0; seg < SEG; seg++) S += g_Spart[(seg * 4 + b) * NPIX + m];
        acc += logf(S * g_vs[idx] + 1e-4f);
    }
    red[t] = acc; __syncthreads();
    for (int s = 128; s > 0; s >>= 1) { if (t < s) red[t] += red[t + s]; __syncthreads(); }
    if (t == 0) out[0] = red[0] * (1.f / (4.f * NPIX));
}

// ---------------- launch ----------------
extern "C" void kernel_launch(void* const* d_in, const int* in_sizes, int n_in,
                              void* d_out, int out_size) {
    const float* input_a = (const float*)d_in[0];
    const float* input_b = (const float*)d_in[1];
    const float* w1      = (const float*)d_in[2];
    const float* b1      = (const float*)d_in[3];
    const float* w2      = (const float*)d_in[4];
    const float* b2      = (const float*)d_in[5];
    const float* noise   = (const float*)d_in[6];
    const int*   u_roll  = (const int*)d_in[7];
    const int*   v_roll  = (const int*)d_in[8];
    const int*   swap    = (const int*)d_in[9];
    float* out = (float*)d_out;

    cudaFuncSetAttribute(gemm_hmma_kernel, cudaFuncAttributeMaxDynamicSharedMemorySize, GEMM_SMEM);

    fwd_sample_kernel<<<(16 * 3 * NPIX + 255) / 256, 256>>>(input_a, input_b, noise, swap, u_roll, v_roll);
    conv3_kernel<<<(16 * HIDC * NPIX + 255) / 256, 256>>>(w1, b1);
    bwdconv1_kernel<<<16 * NPIX, FEATC>>>(w2, b2, noise, swap, u_roll, v_roll);
    gemm_hmma_kernel<<<dim3(29, 29, 8), 256, GEMM_SMEM>>>();
    rowstats_kernel<<<4 * NPIX, 256>>>();
    colstats_kernel<<<dim3(15, 4, SEG), 256>>>();
    colmerge_kernel<<<(4 * NPIX + 255) / 256, 256>>>();
    spart_kernel<<<dim3(15, 4, SEG), 256>>>();
    final_kernel<<<1, 256>>>(out);
}

// round 5
// speedup vs baseline: 1.4261x; 1.1232x over previous
#include <cuda_runtime.h>
#include <cuda_fp16.h>
#include <stdint.h>

#define HW    60
#define NPIX  3600
#define HIDC  64
#define FEATC 128
#define MSIZE (3600LL*3600LL)
#define SEG   8
#define SEGN  450   /* 3600/8 */
#define NTIL  29    /* ceil(3600/128) */

// ---------------- static device scratch (no allocations allowed) ----------------
__device__ float g_xw[16*3*NPIX];            // forward-warped inputs
__device__ float g_h1[16*HIDC*NPIX];         // conv3x3+relu
__device__ __half g_Fh[16L*NPIX*FEATC];      // features hi (fp16)
__device__ __half g_Fl[16L*NPIX*FEATC];      // features lo (fp16 residual)
__device__ float g_M [8L*3600*3600];         // [mat*4+b][n][m]; mat0=Mh, mat1=Mv  (~415MB)
__device__ float g_rmax_p[NTIL*4*NPIX], g_rsum_p[NTIL*4*NPIX];  // Mh row partials per col-tile bx
__device__ float g_cmax_p[NTIL*4*NPIX], g_csum_p[NTIL*4*NPIX];  // Mv col partials per row-tile by
__device__ float g_hmax[4*NPIX], g_hs[4*NPIX];
__device__ float g_vmax[4*NPIX], g_vs[4*NPIX];
__device__ float g_Spart[SEG*4*NPIX];

// Fast exp on the FMA pipe (no MUFU). rel err ~2e-5.
__device__ __forceinline__ float fexp(float x) {
    float t = x * 1.4426950408889634f;
    t = fmaxf(t, -125.0f);
    float r = floorf(t);
    float f = t - r;
    float p = 1.5403530e-4f;
    p = fmaf(p, f, 1.3333558e-3f);
    p = fmaf(p, f, 9.6181291e-3f);
    p = fmaf(p, f, 5.5504109e-2f);
    p = fmaf(p, f, 2.4022651e-1f);
    p = fmaf(p, f, 6.9314718e-1f);
    p = fmaf(p, f, 1.0f);
    int ei = (int)r;
    return __int_as_float((ei + 127) << 23) * p;
}

// theta for instance-batch ib
__device__ __forceinline__ void compute_theta(const float* __restrict__ noise, int swp, int ib,
                                              float* TA, float* TB) {
    const float* nz = noise + ib * 9;
    float a  = 1.f + 0.05f * nz[0], b = 0.05f * nz[1], c = 0.05f * nz[2];
    float d  = 0.05f * nz[3], e = 1.f + 0.05f * nz[4], f = 0.05f * nz[5];
    float id = 1.f / (a * e - b * d);
    float fwd[6] = {a, b, c, d, e, f};
    float bwd[6] = { e * id, -b * id, (b * f - c * e) * id,
                    -d * id,  a * id, (c * d - a * f) * id};
    bool s = (swp == 1);
#pragma unroll
    for (int k = 0; k < 6; k++) {
        if (TA) TA[k] = s ? bwd[k] : fwd[k];
        if (TB) TB[k] = s ? fwd[k] : bwd[k];
    }
}

// ---------------- K1: forward grid_sample with fused roll + inline theta ----------------
__global__ void fwd_sample_kernel(const float* __restrict__ inA, const float* __restrict__ inB,
                                  const float* __restrict__ noise, const int* __restrict__ swap,
                                  const int* __restrict__ u_roll, const int* __restrict__ v_roll) {
    int idx = blockIdx.x * blockDim.x + threadIdx.x;
    if (idx >= 16 * 3 * NPIX) return;
    int p  = idx % NPIX;
    int c  = (idx / NPIX) % 3;
    int ib = idx / (3 * NPIX);
    int i  = ib >> 2, b = ib & 3;
    float T[6];
    compute_theta(noise, swap[i], ib, T, nullptr);
    int r = p / HW, cc = p % HW;
    float xn = (2 * cc + 1) * (1.f / HW) - 1.f;
    float yn = (2 * r  + 1) * (1.f / HW) - 1.f;
    float gx = T[0] * xn + T[1] * yn + T[2];
    float gy = T[3] * xn + T[4] * yn + T[5];
    float x = (gx + 1.f) * (HW * 0.5f) - 0.5f;
    float y = (gy + 1.f) * (HW * 0.5f) - 0.5f;
    float x0f = floorf(x), y0f = floorf(y);
    int x0 = (int)x0f, y0 = (int)y0f;
    float wx1 = x - x0f, wx0 = 1.f - wx1;
    float wy1 = y - y0f, wy0 = 1.f - wy1;
    const float* src = ((i & 1) == 0) ? inA : inB;
    src += (b * 3 + c) * NPIX;
    int u = u_roll[ib], v = v_roll[ib];
    float acc = 0.f;
#pragma unroll
    for (int ky = 0; ky < 2; ky++) {
        int iy = y0 + ky;
        if (iy < 0 || iy >= HW) continue;
        int ry = iy + u; if (ry >= HW) ry -= HW;
        float wy = ky ? wy1 : wy0;
#pragma unroll
        for (int kx = 0; kx < 2; kx++) {
            int ix = x0 + kx;
            if (ix < 0 || ix >= HW) continue;
            int rx = ix + v; if (rx >= HW) rx -= HW;
            acc += wy * (kx ? wx1 : wx0) * src[ry * HW + rx];
        }
    }
    g_xw[ib * 3 * NPIX + c * NPIX + p] = acc;
}

// ---------------- K2: conv3x3 (3->64) + relu ----------------
__global__ void conv3_kernel(const float* __restrict__ w1, const float* __restrict__ b1) {
    int idx = blockIdx.x * blockDim.x + threadIdx.x;
    if (idx >= 16 * HIDC * NPIX) return;
    int p  = idx % NPIX;
    int oc = (idx / NPIX) % HIDC;
    int ib = idx / (NPIX * HIDC);
    int r = p / HW, c = p % HW;
    const float* xin = g_xw + ib * 3 * NPIX;
    const float* wk  = w1 + oc * 27;
    float acc = b1[oc];
#pragma unroll
    for (int ci = 0; ci < 3; ci++)
#pragma unroll
        for (int dy = -1; dy <= 1; dy++) {
            int rr = r + dy;
            if (rr < 0 || rr >= HW) continue;
#pragma unroll
            for (int dx = -1; dx <= 1; dx++) {
                int c2 = c + dx;
                if (c2 < 0 || c2 >= HW) continue;
                acc += wk[ci * 9 + (dy + 1) * 3 + (dx + 1)] * xin[ci * NPIX + rr * HW + c2];
            }
        }
    g_h1[(ib * HIDC + oc) * NPIX + p] = fmaxf(acc, 0.f);
}

// ---------------- K3: fused backward grid_sample + conv1x1 ----------------
__global__ void bwdconv1_kernel(const float* __restrict__ w2, const float* __restrict__ b2,
                                const float* __restrict__ noise, const int* __restrict__ swap,
                                const int* __restrict__ u_roll, const int* __restrict__ v_roll) {
    int blk = blockIdx.x;
    int ib = blk / NPIX, n = blk % NPIX;
    int d  = threadIdx.x;
    __shared__ float wt[4];
    __shared__ int   pp[4];
    __shared__ float sh_h[HIDC];
    __shared__ float sh_ws;
    if (d == 0) {
        float T[6];
        compute_theta(noise, swap[ib >> 2], ib, nullptr, T);
        int u = u_roll[ib], v = v_roll[ib];
        int r = n / HW, c = n % HW;
        int rr = r - u; if (rr < 0) rr += HW;
        int cc = c - v; if (cc < 0) cc += HW;
        float xn = (2 * cc + 1) * (1.f / HW) - 1.f;
        float yn = (2 * rr + 1) * (1.f / HW) - 1.f;
        float gx = T[0] * xn + T[1] * yn + T[2];
        float gy = T[3] * xn + T[4] * yn + T[5];
        float x = (gx + 1.f) * (HW * 0.5f) - 0.5f;
        float y = (gy + 1.f) * (HW * 0.5f) - 0.5f;
        float x0f = floorf(x), y0f = floorf(y);
        int x0 = (int)x0f, y0 = (int)y0f;
        float wx1 = x - x0f, wx0 = 1.f - wx1;
        float wy1 = y - y0f, wy0 = 1.f - wy1;
        float ws = 0.f;
#pragma unroll
        for (int k = 0; k < 4; k++) {
            int iy = y0 + (k >> 1), ix = x0 + (k & 1);
            bool ok = (iy >= 0 && iy < HW && ix >= 0 && ix < HW);
            pp[k] = ok ? (iy * HW + ix) : -1;
            wt[k] = ((k >> 1) ? wy1 : wy0) * ((k & 1) ? wx1 : wx0);
            if (ok) ws += wt[k];
        }
        sh_ws = ws;
    }
    __syncthreads();
    if (d < HIDC) {
        const float* hb = g_h1 + (size_t)(ib * HIDC + d) * NPIX;
        float a = 0.f;
#pragma unroll
        for (int k = 0; k < 4; k++) {
            int q = pp[k];
            if (q >= 0) a += wt[k] * hb[q];
        }
        sh_h[d] = a;
    }
    __syncthreads();
    const float* wr = w2 + d * HIDC;
    float acc = sh_ws * b2[d];
#pragma unroll
    for (int h = 0; h < HIDC; h++) acc = fmaf(wr[h], sh_h[h], acc);
    size_t o = ((size_t)ib * NPIX + n) * FEATC + d;
    __half hv = __float2half_rn(acc);
    g_Fh[o] = hv;
    g_Fl[o] = __float2half_rn(acc - __half2float(hv));
}

// ---------------- K4: split-fp16 HMMA GEMM + fused per-tile softmax stats ----------------
#define SA_HI 0
#define SA_LO 32768
#define SB_OFF 65536
#define GEMM_SMEM 98304
__device__ __forceinline__ uint32_t sw_off(int r, int c16) {
    return (uint32_t)(r * 256 + ((((c16 ^ r) & 7)) | (c16 & 8)) * 16);
}
__device__ __forceinline__ uint32_t smem_u32(const void* p) {
    uint32_t a;
    asm("{ .reg .u64 t; cvta.to.shared.u64 t, %1; cvt.u32.u64 %0, t; }" : "=r"(a) : "l"(p));
    return a;
}
#define LDSM_X4(R0, R1, R2, R3, addr)                                             \
    asm volatile("ldmatrix.sync.aligned.m8n8.x4.shared.b16 {%0,%1,%2,%3}, [%4];"  \
                 : "=r"(R0), "=r"(R1), "=r"(R2), "=r"(R3) : "r"(addr))
#define HMMA16816(D, A0, A1, A2, A3, B0, B1)                                      \
    asm volatile("mma.sync.aligned.m16n8k16.row.col.f32.f16.f16.f32 "             \
                 "{%0,%1,%2,%3}, {%4,%5,%6,%7}, {%8,%9}, {%0,%1,%2,%3};\n"        \
                 : "+f"(D[0]), "+f"(D[1]), "+f"(D[2]), "+f"(D[3])                 \
                 : "r"(A0), "r"(A1), "r"(A2), "r"(A3), "r"(B0), "r"(B1))

__global__ __launch_bounds__(256, 2) void gemm_hmma_kernel() {
    extern __shared__ char smem[];
    uint32_t sb = smem_u32(smem);
    int z = blockIdx.z;                       // mat*4 + b
    int mat = z >> 2, b = z & 3;
    size_t baseA = (size_t)((mat * 2)     * 4 + b) * NPIX * FEATC;
    size_t baseB = (size_t)((mat * 2 + 1) * 4 + b) * NPIX * FEATC;
    float* C = g_M + (size_t)z * MSIZE;
    int n0 = blockIdx.y * 128, m0 = blockIdx.x * 128;
    int tid = threadIdx.x;
    int wid = tid >> 5, lane = tid & 31;
    int wr = wid >> 2, wc = wid & 3;          // warp: rows wr*64(4 mt), cols wc*32(4 nt)

    // ---- copy A hi+lo ----
    {
        const uint4* srcH = (const uint4*)(g_Fh + baseA);
        const uint4* srcL = (const uint4*)(g_Fl + baseA);
#pragma unroll
        for (int i = 0; i < 16; i++) {
            int slot = tid + i * 256;
            int c16 = slot & 15, row = (slot >> 4) & 127, p = slot >> 11;
            int gr = n0 + row;
            uint4 v = make_uint4(0, 0, 0, 0);
            if (gr < NPIX) v = (p ? srcL : srcH)[gr * 16 + c16];
            *(uint4*)(smem + (p ? SA_LO : SA_HI) + sw_off(row, c16)) = v;
        }
    }
    // ---- copy B hi ----
    {
        const uint4* srcH = (const uint4*)(g_Fh + baseB);
#pragma unroll
        for (int i = 0; i < 8; i++) {
            int slot = tid + i * 256;
            int c16 = slot & 15, row = slot >> 4;
            int gm = m0 + row;
            uint4 v = make_uint4(0, 0, 0, 0);
            if (gm < NPIX) v = srcH[gm * 16 + c16];
            *(uint4*)(smem + SB_OFF + sw_off(row, c16)) = v;
        }
    }
    __syncthreads();

    float acc[4][4][4];
#pragma unroll
    for (int u = 0; u < 4; u++)
#pragma unroll
        for (int v = 0; v < 4; v++)
#pragma unroll
            for (int r = 0; r < 4; r++) acc[u][v][r] = 0.f;

    int a_row_l = ((lane >> 3) & 1) * 8 + (lane & 7);
    int a_c16_l = (lane >> 4);
    int b_row_l = ((lane >> 4) * 8) + (lane & 7);
    int b_c16_l = ((lane >> 3) & 1);

    // ---- phase 1: B=hi (hi*hi + lo*hi) ----
#pragma unroll
    for (int kt = 0; kt < 8; kt++) {
        uint32_t ah[4][4], al[4][4], bf[4][2];
#pragma unroll
        for (int mt = 0; mt < 4; mt++) {
            uint32_t off = sw_off(wr * 64 + mt * 16 + a_row_l, 2 * kt + a_c16_l);
            LDSM_X4(ah[mt][0], ah[mt][1], ah[mt][2], ah[mt][3], sb + SA_HI + off);
            LDSM_X4(al[mt][0], al[mt][1], al[mt][2], al[mt][3], sb + SA_LO + off);
        }
#pragma unroll
        for (int np = 0; np < 2; np++) {
            uint32_t off = sw_off(wc * 32 + np * 16 + b_row_l, 2 * kt + b_c16_l);
            LDSM_X4(bf[np * 2][0], bf[np * 2][1], bf[np * 2 + 1][0], bf[np * 2 + 1][1], sb + SB_OFF + off);
        }
#pragma unroll
        for (int mt = 0; mt < 4; mt++)
#pragma unroll
            for (int nt = 0; nt < 4; nt++) {
                HMMA16816(acc[mt][nt], ah[mt][0], ah[mt][1], ah[mt][2], ah[mt][3], bf[nt][0], bf[nt][1]);
                HMMA16816(acc[mt][nt], al[mt][0], al[mt][1], al[mt][2], al[mt][3], bf[nt][0], bf[nt][1]);
            }
    }
    __syncthreads();
    // ---- copy B lo ----
    {
        const uint4* srcL = (const uint4*)(g_Fl + baseB);
#pragma unroll
        for (int i = 0; i < 8; i++) {
            int slot = tid + i * 256;
            int c16 = slot & 15, row = slot >> 4;
            int gm = m0 + row;
            uint4 v = make_uint4(0, 0, 0, 0);
            if (gm < NPIX) v = srcL[gm * 16 + c16];
            *(uint4*)(smem + SB_OFF + sw_off(row, c16)) = v;
        }
    }
    __syncthreads();
    // ---- phase 2: B=lo (hi*lo) ----
#pragma unroll
    for (int kt = 0; kt < 8; kt++) {
        uint32_t ah[4][4], bf[4][2];
#pragma unroll
        for (int mt = 0; mt < 4; mt++) {
            uint32_t off = sw_off(wr * 64 + mt * 16 + a_row_l, 2 * kt + a_c16_l);
            LDSM_X4(ah[mt][0], ah[mt][1], ah[mt][2], ah[mt][3], sb + SA_HI + off);
        }
#pragma unroll
        for (int np = 0; np < 2; np++) {
            uint32_t off = sw_off(wc * 32 + np * 16 + b_row_l, 2 * kt + b_c16_l);
            LDSM_X4(bf[np * 2][0], bf[np * 2][1], bf[np * 2 + 1][0], bf[np * 2 + 1][1], sb + SB_OFF + off);
        }
#pragma unroll
        for (int mt = 0; mt < 4; mt++)
#pragma unroll
            for (int nt = 0; nt < 4; nt++)
                HMMA16816(acc[mt][nt], ah[mt][0], ah[mt][1], ah[mt][2], ah[mt][3], bf[nt][0], bf[nt][1]);
    }

    // ---- store C ----
    int g = lane >> 2, t4 = lane & 3;
#pragma unroll
    for (int mt = 0; mt < 4; mt++) {
        int r0 = n0 + wr * 64 + mt * 16 + g;
#pragma unroll
        for (int nt = 0; nt < 4; nt++) {
            int col = m0 + wc * 32 + nt * 8 + 2 * t4;
            if (col < NPIX) {
                if (r0 < NPIX)
                    *(float2*)&C[(size_t)r0 * NPIX + col] = make_float2(acc[mt][nt][0], acc[mt][nt][1]);
                if (r0 + 8 < NPIX)
                    *(float2*)&C[(size_t)(r0 + 8) * NPIX + col] = make_float2(acc[mt][nt][2], acc[mt][nt][3]);
            }
        }
    }

    // ---- fused per-tile softmax stats ----
    __syncthreads();                            // smem B region free now
    float* s_a   = (float*)(smem + SB_OFF);     // [4][128]
    float* s_fin = (float*)(smem + SB_OFF + 2048); // [128]

    if (mat == 0) {
        // Mh: per-row stats over this tile's 128 cols
        float rmx[4][2];
#pragma unroll
        for (int mt = 0; mt < 4; mt++)
#pragma unroll
            for (int h = 0; h < 2; h++) {
                float v = -1e30f;
#pragma unroll
                for (int nt = 0; nt < 4; nt++)
#pragma unroll
                    for (int k = 0; k < 2; k++) {
                        int col = m0 + wc * 32 + nt * 8 + 2 * t4 + k;
                        float x = (col < NPIX) ? acc[mt][nt][h * 2 + k] : -1e30f;
                        v = fmaxf(v, x);
                    }
                rmx[mt][h] = v;
            }
#pragma unroll
        for (int o = 1; o < 4; o <<= 1)
#pragma unroll
            for (int mt = 0; mt < 4; mt++)
#pragma unroll
                for (int h = 0; h < 2; h++)
                    rmx[mt][h] = fmaxf(rmx[mt][h], __shfl_xor_sync(0xffffffffu, rmx[mt][h], o));
        if (t4 == 0)
#pragma unroll
            for (int mt = 0; mt < 4; mt++)
#pragma unroll
                for (int h = 0; h < 2; h++)
                    s_a[wc * 128 + wr * 64 + mt * 16 + h * 8 + g] = rmx[mt][h];
        __syncthreads();
        if (tid < 128)
            s_fin[tid] = fmaxf(fmaxf(s_a[tid], s_a[128 + tid]), fmaxf(s_a[256 + tid], s_a[384 + tid]));
        __syncthreads();
        float rsm[4][2];
#pragma unroll
        for (int mt = 0; mt < 4; mt++)
#pragma unroll
            for (int h = 0; h < 2; h++) {
                float fm = s_fin[wr * 64 + mt * 16 + h * 8 + g];
                float sa = 0.f;
#pragma unroll
                for (int nt = 0; nt < 4; nt++)
#pragma unroll
                    for (int k = 0; k < 2; k++) {
                        int col = m0 + wc * 32 + nt * 8 + 2 * t4 + k;
                        float x = (col < NPIX) ? acc[mt][nt][h * 2 + k] : -1e30f;
                        sa += fexp(x - fm);
                    }
                rsm[mt][h] = sa;
            }
#pragma unroll
        for (int o = 1; o < 4; o <<= 1)
#pragma unroll
            for (int mt = 0; mt < 4; mt++)
#pragma unroll
                for (int h = 0; h < 2; h++)
                    rsm[mt][h] += __shfl_xor_sync(0xffffffffu, rsm[mt][h], o);
        __syncthreads();
        if (t4 == 0)
#pragma unroll
            for (int mt = 0; mt < 4; mt++)
#pragma unroll
                for (int h = 0; h < 2; h++)
                    s_a[wc * 128 + wr * 64 + mt * 16 + h * 8 + g] = rsm[mt][h];
        __syncthreads();
        if (tid < 128) {
            int n = n0 + tid;
            if (n < NPIX) {
                int o = (blockIdx.x * 4 + b) * NPIX + n;
                g_rmax_p[o] = s_fin[tid];
                g_rsum_p[o] = s_a[tid] + s_a[128 + tid] + s_a[256 + tid] + s_a[384 + tid];
            }
        }
    } else {
        // Mv: per-col stats over this tile's 128 rows
        float cmx[4][2];
#pragma unroll
        for (int nt = 0; nt < 4; nt++)
#pragma unroll
            for (int k = 0; k < 2; k++) {
                float v = -1e30f;
#pragma unroll
                for (int mt = 0; mt < 4; mt++)
#pragma unroll
                    for (int h = 0; h < 2; h++) {
                        int row = n0 + wr * 64 + mt * 16 + h * 8 + g;
                        float x = (row < NPIX) ? acc[mt][nt][h * 2 + k] : -1e30f;
                        v = fmaxf(v, x);
                    }
                cmx[nt][k] = v;
            }
#pragma unroll
        for (int o = 4; o < 32; o <<= 1)
#pragma unroll
            for (int nt = 0; nt < 4; nt++)
#pragma unroll
                for (int k = 0; k < 2; k++)
                    cmx[nt][k] = fmaxf(cmx[nt][k], __shfl_xor_sync(0xffffffffu, cmx[nt][k], o));
        if (g == 0)
#pragma unroll
            for (int nt = 0; nt < 4; nt++)
#pragma unroll
                for (int k = 0; k < 2; k++)
                    s_a[wr * 128 + wc * 32 + nt * 8 + 2 * t4 + k] = cmx[nt][k];
        __syncthreads();
        if (tid < 128)
            s_fin[tid] = fmaxf(fmaxf(s_a[tid], s_a[128 + tid]), fmaxf(s_a[256 + tid], s_a[384 + tid]));
        __syncthreads();
        float csm[4][2];
#pragma unroll
        for (int nt = 0; nt < 4; nt++)
#pragma unroll
            for (int k = 0; k < 2; k++) {
                float fm = s_fin[wc * 32 + nt * 8 + 2 * t4 + k];
                float sa = 0.f;
#pragma unroll
                for (int mt = 0; mt < 4; mt++)
#pragma unroll
                    for (int h = 0; h < 2; h++) {
                        int row = n0 + wr * 64 + mt * 16 + h * 8 + g;
                        float x = (row < NPIX) ? acc[mt][nt][h * 2 + k] : -1e30f;
                        sa += fexp(x - fm);
                    }
                csm[nt][k] = sa;
            }
#pragma unroll
        for (int o = 4; o < 32; o <<= 1)
#pragma unroll
            for (int nt = 0; nt < 4; nt++)
#pragma unroll
                for (int k = 0; k < 2; k++)
                    csm[nt][k] += __shfl_xor_sync(0xffffffffu, csm[nt][k], o);
        __syncthreads();
        if (g == 0)
#pragma unroll
            for (int nt = 0; nt < 4; nt++)
#pragma unroll
                for (int k = 0; k < 2; k++)
                    s_a[wr * 128 + wc * 32 + nt * 8 + 2 * t4 + k] = csm[nt][k];
        __syncthreads();
        if (tid < 128) {
            int m = m0 + tid;
            if (m < NPIX) {
                int o = (blockIdx.y * 4 + b) * NPIX + m;
                g_cmax_p[o] = s_fin[tid];
                g_csum_p[o] = s_a[tid] + s_a[128 + tid] + s_a[256 + tid] + s_a[384 + tid];
            }
        }
    }
}

// ---------------- K5a: merge Mh row partials over col tiles ----------------
__global__ void hmerge_kernel() {
    int idx = blockIdx.x * blockDim.x + threadIdx.x;
    if (idx >= 4 * NPIX) return;
    int b = idx / NPIX, n = idx % NPIX;
    float mx = -1e30f;
#pragma unroll
    for (int t = 0; t < NTIL; t++) mx = fmaxf(mx, g_rmax_p[(t * 4 + b) * NPIX + n]);
    float s = 0.f;
#pragma unroll
    for (int t = 0; t < NTIL; t++)
        s += g_rsum_p[(t * 4 + b) * NPIX + n] * fexp(g_rmax_p[(t * 4 + b) * NPIX + n] - mx);
    g_hmax[idx] = mx;
    g_hs[idx]   = 1.f / (s + 1e-4f);
}

// ---------------- K5b: merge Mv col partials over row tiles ----------------
__global__ void vmerge_kernel() {
    int idx = blockIdx.x * blockDim.x + threadIdx.x;
    if (idx >= 4 * NPIX) return;
    int b = idx / NPIX, m = idx % NPIX;
    float mx = -1e30f;
#pragma unroll
    for (int t = 0; t < NTIL; t++) mx = fmaxf(mx, g_cmax_p[(t * 4 + b) * NPIX + m]);
    float s = 0.f;
#pragma unroll
    for (int t = 0; t < NTIL; t++)
        s += g_csum_p[(t * 4 + b) * NPIX + m] * fexp(g_cmax_p[(t * 4 + b) * NPIX + m] - mx);
    g_vmax[idx] = mx;
    g_vs[idx]   = 1.f / (s + 1e-4f);
}

// ---------------- K6: S[b,m] partial sums, MLP-batched streaming loads ----------------
__global__ void spart_kernel() {
    int m = blockIdx.x * 256 + threadIdx.x;
    int b = blockIdx.y, seg = blockIdx.z;
    if (m >= NPIX) return;
    const float* Mh = g_M + (size_t)b * MSIZE;
    const float* Mv = g_M + (size_t)(4 + b) * MSIZE;
    float vmaxm = g_vmax[b * NPIX + m];
    float s = 0.f;
    int n0 = seg * SEGN;
    for (int nb = 0; nb < SEGN; nb += 6) {       // 450/6 = 75
        float e[6];
#pragma unroll
        for (int j = 0; j < 6; j++) {
            int n = n0 + nb + j;
            float a = __ldcs(&Mv[(size_t)n * NPIX + m]);
            float c = __ldcs(&Mh[(size_t)n * NPIX + m]);
            e[j] = a + c - g_hmax[b * NPIX + n];
        }
#pragma unroll
        for (int j = 0; j < 6; j++)
            s = fmaf(fexp(e[j] - vmaxm), g_hs[b * NPIX + n0 + nb + j], s);
    }
    g_Spart[(seg * 4 + b) * NPIX + m] = s;
}

// ---------------- K7: deterministic final reduction ----------------
__global__ void final_kernel(float* __restrict__ out) {
    __shared__ float red[256];
    int t = threadIdx.x;
    float acc = 0.f;
    for (int idx = t; idx < 4 * NPIX; idx += 256) {
        int b = idx / NPIX, m = idx % NPIX;
        float S = 0.f;
#pragma unroll
        for (int seg = 0; seg < SEG; seg++) S += g_Spart[(seg * 4 + b) * NPIX + m];
        acc += logf(S * g_vs[idx] + 1e-4f);
    }
    red[t] = acc; __syncthreads();
    for (int s = 128; s > 0; s >>= 1) { if (t < s) red[t] += red[t + s]; __syncthreads(); }
    if (t == 0) out[0] = red[0] * (1.f / (4.f * NPIX));
}

// ---------------- launch ----------------
extern "C" void kernel_launch(void* const* d_in, const int* in_sizes, int n_in,
                              void* d_out, int out_size) {
    const float* input_a = (const float*)d_in[0];
    const float* input_b = (const float*)d_in[1];
    const float* w1      = (const float*)d_in[2];
    const float* b1      = (const float*)d_in[3];
    const float* w2      = (const float*)d_in[4];
    const float* b2      = (const float*)d_in[5];
    const float* noise   = (const float*)d_in[6];
    const int*   u_roll  = (const int*)d_in[7];
    const int*   v_roll  = (const int*)d_in[8];
    const int*   swap    = (const int*)d_in[9];
    float* out = (float*)d_out;

    cudaFuncSetAttribute(gemm_hmma_kernel, cudaFuncAttributeMaxDynamicSharedMemorySize, GEMM_SMEM);

    fwd_sample_kernel<<<(16 * 3 * NPIX + 255) / 256, 256>>>(input_a, input_b, noise, swap, u_roll, v_roll);
    conv3_kernel<<<(16 * HIDC * NPIX + 255) / 256, 256>>>(w1, b1);
    bwdconv1_kernel<<<16 * NPIX, FEATC>>>(w2, b2, noise, swap, u_roll, v_roll);
    gemm_hmma_kernel<<<dim3(NTIL, NTIL, 8), 256, GEMM_SMEM>>>();
    hmerge_kernel<<<(4 * NPIX + 255) / 256, 256>>>();
    vmerge_kernel<<<(4 * NPIX + 255) / 256, 256>>>();
    spart_kernel<<<dim3(15, 4, SEG), 256>>>();
    final_kernel<<<1, 256>>>(out);
}

// round 7
// speedup vs baseline: 5.4193x; 3.8002x over previous
#include <cuda_runtime.h>
#include <cuda_fp16.h>
#include <stdint.h>

#define HW    60
#define NPIX  3600
#define HIDC  64
#define FEATC 128
#define MSIZE (3600LL*3600LL)
#define SEG   8
#define SEGN  450   /* 3600/8 */
#define NTIL  29    /* ceil(3600/128) */
#define PIXB  64    /* pixels per bwdconv1 block */

// ---------------- static device scratch (no allocations allowed) ----------------
__device__ float g_xw[16*3*NPIX];            // forward-warped inputs
__device__ float g_h1[16L*NPIX*HIDC];        // conv3x3+relu, TRANSPOSED: [ib][pix][ch]
__device__ __half g_Fh[16L*NPIX*FEATC];      // features hi (fp16)
__device__ __half g_Fl[16L*NPIX*FEATC];      // features lo (fp16 residual)
__device__ float g_M [8L*3600*3600];         // [mat*4+b][n][m]; mat0=Mh, mat1=Mv  (~415MB)
__device__ float g_rmax_p[NTIL*4*NPIX], g_rsum_p[NTIL*4*NPIX];
__device__ float g_cmax_p[NTIL*4*NPIX], g_csum_p[NTIL*4*NPIX];
__device__ float g_hmax[4*NPIX], g_hs[4*NPIX];
__device__ float g_vmax[4*NPIX], g_vs[4*NPIX];
__device__ float g_Spart[SEG*4*NPIX];

// Fast exp on the FMA pipe (no MUFU). rel err ~2e-5.
__device__ __forceinline__ float fexp(float x) {
    float t = x * 1.4426950408889634f;
    t = fmaxf(t, -125.0f);
    float r = floorf(t);
    float f = t - r;
    float p = 1.5403530e-4f;
    p = fmaf(p, f, 1.3333558e-3f);
    p = fmaf(p, f, 9.6181291e-3f);
    p = fmaf(p, f, 5.5504109e-2f);
    p = fmaf(p, f, 2.4022651e-1f);
    p = fmaf(p, f, 6.9314718e-1f);
    p = fmaf(p, f, 1.0f);
    int ei = (int)r;
    return __int_as_float((ei + 127) << 23) * p;
}

__device__ __forceinline__ void compute_theta(const float* __restrict__ noise, int swp, int ib,
                                              float* TA, float* TB) {
    const float* nz = noise + ib * 9;
    float a  = 1.f + 0.05f * nz[0], b = 0.05f * nz[1], c = 0.05f * nz[2];
    float d  = 0.05f * nz[3], e = 1.f + 0.05f * nz[4], f = 0.05f * nz[5];
    float id = 1.f / (a * e - b * d);
    float fwd[6] = {a, b, c, d, e, f};
    float bwd[6] = { e * id, -b * id, (b * f - c * e) * id,
                    -d * id,  a * id, (c * d - a * f) * id};
    bool s = (swp == 1);
#pragma unroll
    for (int k = 0; k < 6; k++) {
        if (TA) TA[k] = s ? bwd[k] : fwd[k];
        if (TB) TB[k] = s ? fwd[k] : bwd[k];
    }
}

// ---------------- K1: forward grid_sample with fused roll + inline theta ----------------
__global__ void fwd_sample_kernel(const float* __restrict__ inA, const float* __restrict__ inB,
                                  const float* __restrict__ noise, const int* __restrict__ swap,
                                  const int* __restrict__ u_roll, const int* __restrict__ v_roll) {
    int idx = blockIdx.x * blockDim.x + threadIdx.x;
    if (idx >= 16 * 3 * NPIX) return;
    int p  = idx % NPIX;
    int c  = (idx / NPIX) % 3;
    int ib = idx / (3 * NPIX);
    int i  = ib >> 2, b = ib & 3;
    float T[6];
    compute_theta(noise, swap[i], ib, T, nullptr);
    int r = p / HW, cc = p % HW;
    float xn = (2 * cc + 1) * (1.f / HW) - 1.f;
    float yn = (2 * r  + 1) * (1.f / HW) - 1.f;
    float gx = T[0] * xn + T[1] * yn + T[2];
    float gy = T[3] * xn + T[4] * yn + T[5];
    float x = (gx + 1.f) * (HW * 0.5f) - 0.5f;
    float y = (gy + 1.f) * (HW * 0.5f) - 0.5f;
    float x0f = floorf(x), y0f = floorf(y);
    int x0 = (int)x0f, y0 = (int)y0f;
    float wx1 = x - x0f, wx0 = 1.f - wx1;
    float wy1 = y - y0f, wy0 = 1.f - wy1;
    const float* src = ((i & 1) == 0) ? inA : inB;
    src += (b * 3 + c) * NPIX;
    int u = u_roll[ib], v = v_roll[ib];
    float acc = 0.f;
#pragma unroll
    for (int ky = 0; ky < 2; ky++) {
        int iy = y0 + ky;
        if (iy < 0 || iy >= HW) continue;
        int ry = iy + u; if (ry >= HW) ry -= HW;
        float wy = ky ? wy1 : wy0;
#pragma unroll
        for (int kx = 0; kx < 2; kx++) {
            int ix = x0 + kx;
            if (ix < 0 || ix >= HW) continue;
            int rx = ix + v; if (rx >= HW) rx -= HW;
            acc += wy * (kx ? wx1 : wx0) * src[ry * HW + rx];
        }
    }
    g_xw[ib * 3 * NPIX + c * NPIX + p] = acc;
}

// ---------------- K2: conv3x3 (3->64) + relu, TRANSPOSED output [ib][pix][ch] ----------------
__global__ void conv3_kernel(const float* __restrict__ w1, const float* __restrict__ b1) {
    int idx = blockIdx.x * blockDim.x + threadIdx.x;
    if (idx >= 16 * HIDC * NPIX) return;
    int p  = idx % NPIX;
    int oc = (idx / NPIX) % HIDC;
    int ib = idx / (NPIX * HIDC);
    int r = p / HW, c = p % HW;
    const float* xin = g_xw + ib * 3 * NPIX;
    const float* wk  = w1 + oc * 27;
    float acc = b1[oc];
#pragma unroll
    for (int ci = 0; ci < 3; ci++)
#pragma unroll
        for (int dy = -1; dy <= 1; dy++) {
            int rr = r + dy;
            if (rr < 0 || rr >= HW) continue;
#pragma unroll
            for (int dx = -1; dx <= 1; dx++) {
                int c2 = c + dx;
                if (c2 < 0 || c2 >= HW) continue;
                acc += wk[ci * 9 + (dy + 1) * 3 + (dx + 1)] * xin[ci * NPIX + rr * HW + c2];
            }
        }
    g_h1[((size_t)ib * NPIX + p) * HIDC + oc] = fmaxf(acc, 0.f);
}

// ---------------- K3: fused backward grid_sample + conv1x1, 64 pixels/block ----------------
// dynamic smem layout (floats):
//   w2s   [0, 128*65)           = 8320 f
//   Hs    [8320, 8320+64*68)    = 4352 f
//   wts   [12672, +256)         = 64*4
//   wss   [12928, +64)
//   pps   [12992, +256) (ints)
#define BW_W2S   0
#define BW_HS    (FEATC * 65)
#define BW_WTS   (BW_HS + PIXB * 68)
#define BW_WSS   (BW_WTS + PIXB * 4)
#define BW_PPS   (BW_WSS + PIXB)
#define BW_SMEM  ((BW_PPS + PIXB * 4) * 4)
__global__ __launch_bounds__(256) void bwdconv1_kernel(
        const float* __restrict__ w2, const float* __restrict__ b2,
        const float* __restrict__ noise, const int* __restrict__ swap,
        const int* __restrict__ u_roll, const int* __restrict__ v_roll) {
    extern __shared__ float smf[];
    float* w2s = smf + BW_W2S;
    float* Hs  = smf + BW_HS;
    float* wts = smf + BW_WTS;   // [pix][4]
    float* wss = smf + BW_WSS;
    int*   pps = (int*)(smf + BW_PPS); // [pix][4]

    int ib = blockIdx.y;
    int p0 = blockIdx.x * PIXB;
    int tid = threadIdx.x;

    // stage w2 into padded smem (coalesced global reads)
    for (int i = tid; i < FEATC * HIDC; i += 256)
        w2s[(i >> 6) * 65 + (i & 63)] = w2[i];

    // phase A: per-pixel taps (threads 0..63)
    if (tid < PIXB) {
        int gp = p0 + tid;
        float T[6];
        compute_theta(noise, swap[ib >> 2], ib, nullptr, T);
        int u = u_roll[ib], v = v_roll[ib];
        int n = (gp < NPIX) ? gp : NPIX - 1;
        int r = n / HW, c = n % HW;
        int rr = r - u; if (rr < 0) rr += HW;
        int cc = c - v; if (cc < 0) cc += HW;
        float xn = (2 * cc + 1) * (1.f / HW) - 1.f;
        float yn = (2 * rr + 1) * (1.f / HW) - 1.f;
        float gx = T[0] * xn + T[1] * yn + T[2];
        float gy = T[3] * xn + T[4] * yn + T[5];
        float x = (gx + 1.f) * (HW * 0.5f) - 0.5f;
        float y = (gy + 1.f) * (HW * 0.5f) - 0.5f;
        float x0f = floorf(x), y0f = floorf(y);
        int x0 = (int)x0f, y0 = (int)y0f;
        float wx1 = x - x0f, wx0 = 1.f - wx1;
        float wy1 = y - y0f, wy0 = 1.f - wy1;
        float ws = 0.f;
#pragma unroll
        for (int k = 0; k < 4; k++) {
            int iy = y0 + (k >> 1), ix = x0 + (k & 1);
            bool ok = (iy >= 0 && iy < HW && ix >= 0 && ix < HW) && (gp < NPIX);
            pps[tid * 4 + k] = ok ? (iy * HW + ix) : -1;
            float w = ((k >> 1) ? wy1 : wy0) * ((k & 1) ? wx1 : wx0);
            wts[tid * 4 + k] = w;
            if (ok) ws += w;
        }
        wss[tid] = ws;
    }
    __syncthreads();

    // phase B: gather H[pix][ch] (coalesced reads of transposed h1)
    const float* hb = g_h1 + (size_t)ib * NPIX * HIDC;
#pragma unroll
    for (int e = 0; e < 16; e++) {
        int idx = tid + e * 256;
        int ch = idx & 63, pix = idx >> 6;
        float a = 0.f;
#pragma unroll
        for (int k = 0; k < 4; k++) {
            int q = pps[pix * 4 + k];
            if (q >= 0) a += wts[pix * 4 + k] * hb[(size_t)q * HIDC + ch];
        }
        Hs[pix * 68 + ch] = a;
    }
    __syncthreads();

    // load w2 row for this thread's d into registers (conflict-free LDS)
    int d = tid & 127;
    float wreg[HIDC];
#pragma unroll
    for (int h = 0; h < HIDC; h++) wreg[h] = w2s[d * 65 + h];
    float bd = b2[d];

    // phase C: outputs — 2 pixels per pass x 32 passes
#pragma unroll 4
    for (int pass = 0; pass < 32; pass++) {
        int pix = pass * 2 + (tid >> 7);
        int gp = p0 + pix;
        float acc = wss[pix] * bd;
        const float4* hv = (const float4*)&Hs[pix * 68];
#pragma unroll
        for (int h4 = 0; h4 < 16; h4++) {
            float4 hvv = hv[h4];
            acc = fmaf(wreg[h4 * 4 + 0], hvv.x, acc);
            acc = fmaf(wreg[h4 * 4 + 1], hvv.y, acc);
            acc = fmaf(wreg[h4 * 4 + 2], hvv.z, acc);
            acc = fmaf(wreg[h4 * 4 + 3], hvv.w, acc);
        }
        if (gp < NPIX) {
            size_t o = ((size_t)ib * NPIX + gp) * FEATC + d;
            __half hvq = __float2half_rn(acc);
            g_Fh[o] = hvq;
            g_Fl[o] = __float2half_rn(acc - __half2float(hvq));
        }
    }
}

// ---------------- K4: split-fp16 HMMA GEMM + fused per-tile softmax stats ----------------
#define SA_HI 0
#define SA_LO 32768
#define SB_OFF 65536
#define GEMM_SMEM 98304
__device__ __forceinline__ uint32_t sw_off(int r, int c16) {
    return (uint32_t)(r * 256 + ((((c16 ^ r) & 7)) | (c16 & 8)) * 16);
}
__device__ __forceinline__ uint32_t smem_u32(const void* p) {
    uint32_t a;
    asm("{ .reg .u64 t; cvta.to.shared.u64 t, %1; cvt.u32.u64 %0, t; }" : "=r"(a) : "l"(p));
    return a;
}
#define LDSM_X4(R0, R1, R2, R3, addr)                                             \
    asm volatile("ldmatrix.sync.aligned.m8n8.x4.shared.b16 {%0,%1,%2,%3}, [%4];"  \
                 : "=r"(R0), "=r"(R1), "=r"(R2), "=r"(R3) : "r"(addr))
#define HMMA16816(D, A0, A1, A2, A3, B0, B1)                                      \
    asm volatile("mma.sync.aligned.m16n8k16.row.col.f32.f16.f16.f32 "             \
                 "{%0,%1,%2,%3}, {%4,%5,%6,%7}, {%8,%9}, {%0,%1,%2,%3};\n"        \
                 : "+f"(D[0]), "+f"(D[1]), "+f"(D[2]), "+f"(D[3])                 \
                 : "r"(A0), "r"(A1), "r"(A2), "r"(A3), "r"(B0), "r"(B1))

__global__ __launch_bounds__(256, 2) void gemm_hmma_kernel() {
    extern __shared__ char smem[];
    uint32_t sb = smem_u32(smem);
    int z = blockIdx.z;
    int mat = z >> 2, b = z & 3;
    size_t baseA = (size_t)((mat * 2)     * 4 + b) * NPIX * FEATC;
    size_t baseB = (size_t)((mat * 2 + 1) * 4 + b) * NPIX * FEATC;
    float* C = g_M + (size_t)z * MSIZE;
    int n0 = blockIdx.y * 128, m0 = blockIdx.x * 128;
    int tid = threadIdx.x;
    int wid = tid >> 5, lane = tid & 31;
    int wr = wid >> 2, wc = wid & 3;

    {
        const uint4* srcH = (const uint4*)(g_Fh + baseA);
        const uint4* srcL = (const uint4*)(g_Fl + baseA);
#pragma unroll
        for (int i = 0; i < 16; i++) {
            int slot = tid + i * 256;
            int c16 = slot & 15, row = (slot >> 4) & 127, p = slot >> 11;
            int gr = n0 + row;
            uint4 v = make_uint4(0, 0, 0, 0);
            if (gr < NPIX) v = (p ? srcL : srcH)[gr * 16 + c16];
            *(uint4*)(smem + (p ? SA_LO : SA_HI) + sw_off(row, c16)) = v;
        }
    }
    {
        const uint4* srcH = (const uint4*)(g_Fh + baseB);
#pragma unroll
        for (int i = 0; i < 8; i++) {
            int slot = tid + i * 256;
            int c16 = slot & 15, row = slot >> 4;
            int gm = m0 + row;
            uint4 v = make_uint4(0, 0, 0, 0);
            if (gm < NPIX) v = srcH[gm * 16 + c16];
            *(uint4*)(smem + SB_OFF + sw_off(row, c16)) = v;
        }
    }
    __syncthreads();

    float acc[4][4][4];
#pragma unroll
    for (int u = 0; u < 4; u++)
#pragma unroll
        for (int v = 0; v < 4; v++)
#pragma unroll
            for (int r = 0; r < 4; r++) acc[u][v][r] = 0.f;

    int a_row_l = ((lane >> 3) & 1) * 8 + (lane & 7);
    int a_c16_l = (lane >> 4);
    int b_row_l = ((lane >> 4) * 8) + (lane & 7);
    int b_c16_l = ((lane >> 3) & 1);

#pragma unroll
    for (int kt = 0; kt < 8; kt++) {
        uint32_t ah[4][4], al[4][4], bf[4][2];
#pragma unroll
        for (int mt = 0; mt < 4; mt++) {
            uint32_t off = sw_off(wr * 64 + mt * 16 + a_row_l, 2 * kt + a_c16_l);
            LDSM_X4(ah[mt][0], ah[mt][1], ah[mt][2], ah[mt][3], sb + SA_HI + off);
            LDSM_X4(al[mt][0], al[mt][1], al[mt][2], al[mt][3], sb + SA_LO + off);
        }
#pragma unroll
        for (int np = 0; np < 2; np++) {
            uint32_t off = sw_off(wc * 32 + np * 16 + b_row_l, 2 * kt + b_c16_l);
            LDSM_X4(bf[np * 2][0], bf[np * 2][1], bf[np * 2 + 1][0], bf[np * 2 + 1][1], sb + SB_OFF + off);
        }
#pragma unroll
        for (int mt = 0; mt < 4; mt++)
#pragma unroll
            for (int nt = 0; nt < 4; nt++) {
                HMMA16816(acc[mt][nt], ah[mt][0], ah[mt][1], ah[mt][2], ah[mt][3], bf[nt][0], bf[nt][1]);
                HMMA16816(acc[mt][nt], al[mt][0], al[mt][1], al[mt][2], al[mt][3], bf[nt][0], bf[nt][1]);
            }
    }
    __syncthreads();
    {
        const uint4* srcL = (const uint4*)(g_Fl + baseB);
#pragma unroll
        for (int i = 0; i < 8; i++) {
            int slot = tid + i * 256;
            int c16 = slot & 15, row = slot >> 4;
            int gm = m0 + row;
            uint4 v = make_uint4(0, 0, 0, 0);
            if (gm < NPIX) v = srcL[gm * 16 + c16];
            *(uint4*)(smem + SB_OFF + sw_off(row, c16)) = v;
        }
    }
    __syncthreads();
#pragma unroll
    for (int kt = 0; kt < 8; kt++) {
        uint32_t ah[4][4], bf[4][2];
#pragma unroll
        for (int mt = 0; mt < 4; mt++) {
            uint32_t off = sw_off(wr * 64 + mt * 16 + a_row_l, 2 * kt + a_c16_l);
            LDSM_X4(ah[mt][0], ah[mt][1], ah[mt][2], ah[mt][3], sb + SA_HI + off);
        }
#pragma unroll
        for (int np = 0; np < 2; np++) {
            uint32_t off = sw_off(wc * 32 + np * 16 + b_row_l, 2 * kt + b_c16_l);
            LDSM_X4(bf[np * 2][0], bf[np * 2][1], bf[np * 2 + 1][0], bf[np * 2 + 1][1], sb + SB_OFF + off);
        }
#pragma unroll
        for (int mt = 0; mt < 4; mt++)
#pragma unroll
            for (int nt = 0; nt < 4; nt++)
                HMMA16816(acc[mt][nt], ah[mt][0], ah[mt][1], ah[mt][2], ah[mt][3], bf[nt][0], bf[nt][1]);
    }

    int g = lane >> 2, t4 = lane & 3;
#pragma unroll
    for (int mt = 0; mt < 4; mt++) {
        int r0 = n0 + wr * 64 + mt * 16 + g;
#pragma unroll
        for (int nt = 0; nt < 4; nt++) {
            int col = m0 + wc * 32 + nt * 8 + 2 * t4;
            if (col < NPIX) {
                if (r0 < NPIX)
                    *(float2*)&C[(size_t)r0 * NPIX + col] = make_float2(acc[mt][nt][0], acc[mt][nt][1]);
                if (r0 + 8 < NPIX)
                    *(float2*)&C[(size_t)(r0 + 8) * NPIX + col] = make_float2(acc[mt][nt][2], acc[mt][nt][3]);
            }
        }
    }

    __syncthreads();
    float* s_a   = (float*)(smem + SB_OFF);
    float* s_fin = (float*)(smem + SB_OFF + 2048);

    if (mat == 0) {
        float rmx[4][2];
#pragma unroll
        for (int mt = 0; mt < 4; mt++)
#pragma unroll
            for (int h = 0; h < 2; h++) {
                float v = -1e30f;
#pragma unroll
                for (int nt = 0; nt < 4; nt++)
#pragma unroll
                    for (int k = 0; k < 2; k++) {
                        int col = m0 + wc * 32 + nt * 8 + 2 * t4 + k;
                        float x = (col < NPIX) ? acc[mt][nt][h * 2 + k] : -1e30f;
                        v = fmaxf(v, x);
                    }
                rmx[mt][h] = v;
            }
#pragma unroll
        for (int o = 1; o < 4; o <<= 1)
#pragma unroll
            for (int mt = 0; mt < 4; mt++)
#pragma unroll
                for (int h = 0; h < 2; h++)
                    rmx[mt][h] = fmaxf(rmx[mt][h], __shfl_xor_sync(0xffffffffu, rmx[mt][h], o));
        if (t4 == 0)
#pragma unroll
            for (int mt = 0; mt < 4; mt++)
#pragma unroll
                for (int h = 0; h < 2; h++)
                    s_a[wc * 128 + wr * 64 + mt * 16 + h * 8 + g] = rmx[mt][h];
        __syncthreads();
        if (tid < 128)
            s_fin[tid] = fmaxf(fmaxf(s_a[tid], s_a[128 + tid]), fmaxf(s_a[256 + tid], s_a[384 + tid]));
        __syncthreads();
        float rsm[4][2];
#pragma unroll
        for (int mt = 0; mt < 4; mt++)
#pragma unroll
            for (int h = 0; h < 2; h++) {
                float fm = s_fin[wr * 64 + mt * 16 + h * 8 + g];
                float sa = 0.f;
#pragma unroll
                for (int nt = 0; nt < 4; nt++)
#pragma unroll
                    for (int k = 0; k < 2; k++) {
                        int col = m0 + wc * 32 + nt * 8 + 2 * t4 + k;
                        float x = (col < NPIX) ? acc[mt][nt][h * 2 + k] : -1e30f;
                        sa += fexp(x - fm);
                    }
                rsm[mt][h] = sa;
            }
#pragma unroll
        for (int o = 1; o < 4; o <<= 1)
#pragma unroll
            for (int mt = 0; mt < 4; mt++)
#pragma unroll
                for (int h = 0; h < 2; h++)
                    rsm[mt][h] += __shfl_xor_sync(0xffffffffu, rsm[mt][h], o);
        __syncthreads();
        if (t4 == 0)
#pragma unroll
            for (int mt = 0; mt < 4; mt++)
#pragma unroll
                for (int h = 0; h < 2; h++)
                    s_a[wc * 128 + wr * 64 + mt * 16 + h * 8 + g] = rsm[mt][h];
        __syncthreads();
        if (tid < 128) {
            int n = n0 + tid;
            if (n < NPIX) {
                int o = (blockIdx.x * 4 + b) * NPIX + n;
                g_rmax_p[o] = s_fin[tid];
                g_rsum_p[o] = s_a[tid] + s_a[128 + tid] + s_a[256 + tid] + s_a[384 + tid];
            }
        }
    } else {
        float cmx[4][2];
#pragma unroll
        for (int nt = 0; nt < 4; nt++)
#pragma unroll
            for (int k = 0; k < 2; k++) {
                float v = -1e30f;
#pragma unroll
                for (int mt = 0; mt < 4; mt++)
#pragma unroll
                    for (int h = 0; h < 2; h++) {
                        int row = n0 + wr * 64 + mt * 16 + h * 8 + g;
                        float x = (row < NPIX) ? acc[mt][nt][h * 2 + k] : -1e30f;
                        v = fmaxf(v, x);
                    }
                cmx[nt][k] = v;
            }
#pragma unroll
        for (int o = 4; o < 32; o <<= 1)
#pragma unroll
            for (int nt = 0; nt < 4; nt++)
#pragma unroll
                for (int k = 0; k < 2; k++)
                    cmx[nt][k] = fmaxf(cmx[nt][k], __shfl_xor_sync(0xffffffffu, cmx[nt][k], o));
        if (g == 0)
#pragma unroll
            for (int nt = 0; nt < 4; nt++)
#pragma unroll
                for (int k = 0; k < 2; k++)
                    s_a[wr * 128 + wc * 32 + nt * 8 + 2 * t4 + k] = cmx[nt][k];
        __syncthreads();
        if (tid < 128)
            s_fin[tid] = fmaxf(fmaxf(s_a[tid], s_a[128 + tid]), fmaxf(s_a[256 + tid], s_a[384 + tid]));
        __syncthreads();
        float csm[4][2];
#pragma unroll
        for (int nt = 0; nt < 4; nt++)
#pragma unroll
            for (int k = 0; k < 2; k++) {
                float fm = s_fin[wc * 32 + nt * 8 + 2 * t4 + k];
                float sa = 0.f;
#pragma unroll
                for (int mt = 0; mt < 4; mt++)
#pragma unroll
                    for (int h = 0; h < 2; h++) {
                        int row = n0 + wr * 64 + mt * 16 + h * 8 + g;
                        float x = (row < NPIX) ? acc[mt][nt][h * 2 + k] : -1e30f;
                        sa += fexp(x - fm);
                    }
                csm[nt][k] = sa;
            }
#pragma unroll
        for (int o = 4; o < 32; o <<= 1)
#pragma unroll
            for (int nt = 0; nt < 4; nt++)
#pragma unroll
                for (int k = 0; k < 2; k++)
                    csm[nt][k] += __shfl_xor_sync(0xffffffffu, csm[nt][k], o);
        __syncthreads();
        if (g == 0)
#pragma unroll
            for (int nt = 0; nt < 4; nt++)
#pragma unroll
                for (int k = 0; k < 2; k++)
                    s_a[wr * 128 + wc * 32 + nt * 8 + 2 * t4 + k] = csm[nt][k];
        __syncthreads();
        if (tid < 128) {
            int m = m0 + tid;
            if (m < NPIX) {
                int o = (blockIdx.y * 4 + b) * NPIX + m;
                g_cmax_p[o] = s_fin[tid];
                g_csum_p[o] = s_a[tid] + s_a[128 + tid] + s_a[256 + tid] + s_a[384 + tid];
            }
        }
    }
}

// ---------------- K5a/K5b: merge partials ----------------
__global__ void hmerge_kernel() {
    int idx = blockIdx.x * blockDim.x + threadIdx.x;
    if (idx >= 4 * NPIX) return;
    int b = idx / NPIX, n = idx % NPIX;
    float mx = -1e30f;
#pragma unroll
    for (int t = 0; t < NTIL; t++) mx = fmaxf(mx, g_rmax_p[(t * 4 + b) * NPIX + n]);
    float s = 0.f;
#pragma unroll
    for (int t = 0; t < NTIL; t++)
        s += g_rsum_p[(t * 4 + b) * NPIX + n] * fexp(g_rmax_p[(t * 4 + b) * NPIX + n] - mx);
    g_hmax[idx] = mx;
    g_hs[idx]   = 1.f / (s + 1e-4f);
}
__global__ void vmerge_kernel() {
    int idx = blockIdx.x * blockDim.x + threadIdx.x;
    if (idx >= 4 * NPIX) return;
    int b = idx / NPIX, m = idx % NPIX;
    float mx = -1e30f;
#pragma unroll
    for (int t = 0; t < NTIL; t++) mx = fmaxf(mx, g_cmax_p[(t * 4 + b) * NPIX + m]);
    float s = 0.f;
#pragma unroll
    for (int t = 0; t < NTIL; t++)
        s += g_csum_p[(t * 4 + b) * NPIX + m] * fexp(g_cmax_p[(t * 4 + b) * NPIX + m] - mx);
    g_vmax[idx] = mx;
    g_vs[idx]   = 1.f / (s + 1e-4f);
}

// ---------------- K6: S[b,m] partial sums, MLP-batched streaming loads ----------------
__global__ void spart_kernel() {
    int m = blockIdx.x * 256 + threadIdx.x;
    int b = blockIdx.y, seg = blockIdx.z;
    if (m >= NPIX) return;
    const float* Mh = g_M + (size_t)b * MSIZE;
    const float* Mv = g_M + (size_t)(4 + b) * MSIZE;
    float vmaxm = g_vmax[b * NPIX + m];
    float s = 0.f;
    int n0 = seg * SEGN;
    for (int nb = 0; nb < SEGN; nb += 6) {
        float e[6];
#pragma unroll
        for (int j = 0; j < 6; j++) {
            int n = n0 + nb + j;
            float a = __ldcs(&Mv[(size_t)n * NPIX + m]);
            float c = __ldcs(&Mh[(size_t)n * NPIX + m]);
            e[j] = a + c - g_hmax[b * NPIX + n];
        }
#pragma unroll
        for (int j = 0; j < 6; j++)
            s = fmaf(fexp(e[j] - vmaxm), g_hs[b * NPIX + n0 + nb + j], s);
    }
    g_Spart[(seg * 4 + b) * NPIX + m] = s;
}

// ---------------- K7: deterministic final reduction ----------------
__global__ void final_kernel(float* __restrict__ out) {
    __shared__ float red[256];
    int t = threadIdx.x;
    float acc = 0.f;
    for (int idx = t; idx < 4 * NPIX; idx += 256) {
        int b = idx / NPIX, m = idx % NPIX;
        float S = 0.f;
#pragma unroll
        for (int seg = 0; seg < SEG; seg++) S += g_Spart[(seg * 4 + b) * NPIX + m];
        acc += logf(S * g_vs[idx] + 1e-4f);
    }
    red[t] = acc; __syncthreads();
    for (int s = 128; s > 0; s >>= 1) { if (t < s) red[t] += red[t + s]; __syncthreads(); }
    if (t == 0) out[0] = red[0] * (1.f / (4.f * NPIX));
}

// ---------------- launch ----------------
extern "C" void kernel_launch(void* const* d_in, const int* in_sizes, int n_in,
                              void* d_out, int out_size) {
    const float* input_a = (const float*)d_in[0];
    const float* input_b = (const float*)d_in[1];
    const float* w1      = (const float*)d_in[2];
    const float* b1      = (const float*)d_in[3];
    const float* w2      = (const float*)d_in[4];
    const float* b2      = (const float*)d_in[5];
    const float* noise   = (const float*)d_in[6];
    const int*   u_roll  = (const int*)d_in[7];
    const int*   v_roll  = (const int*)d_in[8];
    const int*   swap    = (const int*)d_in[9];
    float* out = (float*)d_out;

    cudaFuncSetAttribute(gemm_hmma_kernel, cudaFuncAttributeMaxDynamicSharedMemorySize, GEMM_SMEM);
    cudaFuncSetAttribute(bwdconv1_kernel, cudaFuncAttributeMaxDynamicSharedMemorySize, BW_SMEM);

    fwd_sample_kernel<<<(16 * 3 * NPIX + 255) / 256, 256>>>(input_a, input_b, noise, swap, u_roll, v_roll);
    conv3_kernel<<<(16 * HIDC * NPIX + 255) / 256, 256>>>(w1, b1);
    bwdconv1_kernel<<<dim3((NPIX + PIXB - 1) / PIXB, 16), 256, BW_SMEM>>>(w2, b2, noise, swap, u_roll, v_roll);
    gemm_hmma_kernel<<<dim3(NTIL, NTIL, 8), 256, GEMM_SMEM>>>();
    hmerge_kernel<<<(4 * NPIX + 255) / 256, 256>>>();
    vmerge_kernel<<<(4 * NPIX + 255) / 256, 256>>>();
    spart_kernel<<<dim3(15, 4, SEG), 256>>>();
    final_kernel<<<1, 256>>>(out);
}